// round 11
// baseline (speedup 1.0000x reference)
#include <cuda_runtime.h>
#include <cuda_bf16.h>
#include <cstdint>
#include <math.h>

// Problem constants
#define S_LEN   2048
#define D_MODEL 768
#define H_NUM   12
#define HD      64
#define B_SZ    2
#define M_ROWS  (B_SZ * S_LEN)   // 4096
#define W_ELEMS (D_MODEL * D_MODEL)

// Q pre-scale: 1/sqrt(64) * log2(e)  (softmax done in exp2 domain)
#define ALPHA_Q (0.125f * 1.44269504088896f)

// Scratch (allocation-free rule: __device__ globals). All bf16 hi/lo pairs.
__device__ __nv_bfloat16 g_xh[M_ROWS * D_MODEL];
__device__ __nv_bfloat16 g_xl[M_ROWS * D_MODEL];
__device__ __nv_bfloat16 g_wh[4 * W_ELEMS];
__device__ __nv_bfloat16 g_wl[4 * W_ELEMS];
__device__ __nv_bfloat16 g_qh[M_ROWS * D_MODEL];
__device__ __nv_bfloat16 g_ql[M_ROWS * D_MODEL];
__device__ __nv_bfloat16 g_kh[M_ROWS * D_MODEL];
__device__ __nv_bfloat16 g_kl[M_ROWS * D_MODEL];
__device__ __nv_bfloat16 g_vh[M_ROWS * D_MODEL];
__device__ __nv_bfloat16 g_vl[M_ROWS * D_MODEL];
__device__ __nv_bfloat16 g_ch[M_ROWS * D_MODEL];
__device__ __nv_bfloat16 g_cl[M_ROWS * D_MODEL];

// ===========================================================================
// Warp-MMA + async-copy helpers
// ===========================================================================
__device__ __forceinline__ uint32_t smem_to_u32(const void* p) {
    uint32_t a;
    asm("{ .reg .u64 t; cvta.to.shared.u64 t, %1; cvt.u32.u64 %0, t; }"
        : "=r"(a) : "l"(p));
    return a;
}
__device__ __forceinline__ void ldsm_x4(uint32_t* r, uint32_t addr) {
    asm volatile(
        "ldmatrix.sync.aligned.m8n8.x4.shared.b16 {%0,%1,%2,%3}, [%4];"
        : "=r"(r[0]), "=r"(r[1]), "=r"(r[2]), "=r"(r[3]) : "r"(addr));
}
__device__ __forceinline__ void ldsm_x4_t(uint32_t* r, uint32_t addr) {
    asm volatile(
        "ldmatrix.sync.aligned.m8n8.x4.trans.shared.b16 {%0,%1,%2,%3}, [%4];"
        : "=r"(r[0]), "=r"(r[1]), "=r"(r[2]), "=r"(r[3]) : "r"(addr));
}
__device__ __forceinline__ void mma_bf16(float* c, const uint32_t* a,
                                         uint32_t b0, uint32_t b1) {
    asm volatile(
        "mma.sync.aligned.m16n8k16.row.col.f32.bf16.bf16.f32 "
        "{%0,%1,%2,%3}, {%4,%5,%6,%7}, {%8,%9}, {%0,%1,%2,%3};"
        : "+f"(c[0]), "+f"(c[1]), "+f"(c[2]), "+f"(c[3])
        : "r"(a[0]), "r"(a[1]), "r"(a[2]), "r"(a[3]), "r"(b0), "r"(b1));
}
__device__ __forceinline__ uint32_t cvt_bf16x2(float lo, float hi) {
    uint32_t r;
    asm("cvt.rn.bf16x2.f32 %0, %1, %2;" : "=r"(r) : "f"(hi), "f"(lo));
    return r;
}
__device__ __forceinline__ float bf16_rt(float x) {
    return __bfloat162float(__float2bfloat16(x));
}
__device__ __forceinline__ void cp_async16(uint32_t dst, const void* src) {
    asm volatile("cp.async.cg.shared.global [%0], [%1], 16;"
                 :: "r"(dst), "l"(src) : "memory");
}
#define CP_COMMIT() asm volatile("cp.async.commit_group;" ::: "memory")
#define CP_WAIT1()  asm volatile("cp.async.wait_group 1;" ::: "memory")
#define CP_WAIT0()  asm volatile("cp.async.wait_group 0;" ::: "memory")

// ===========================================================================
// Fused split: fp32 -> (bf16 hi, bf16 lo) for x + 4 weights in ONE launch.
// ===========================================================================
__global__ __launch_bounds__(256) void split_all_kernel(
    const float* __restrict__ x,
    const float* __restrict__ Wq, const float* __restrict__ Wk,
    const float* __restrict__ Wv, const float* __restrict__ Wo,
    __nv_bfloat16* __restrict__ xh, __nv_bfloat16* __restrict__ xl,
    __nv_bfloat16* __restrict__ wh, __nv_bfloat16* __restrict__ wl)
{
    const int t = blockIdx.y;
    const float* src;
    __nv_bfloat16 *hi, *lo;
    int n4;
    if (t == 0) { src = x;  hi = xh; lo = xl; n4 = M_ROWS * D_MODEL / 4; }
    else {
        const float* ws[4] = {Wq, Wk, Wv, Wo};
        src = ws[t - 1];
        hi = wh + (size_t)(t - 1) * W_ELEMS;
        lo = wl + (size_t)(t - 1) * W_ELEMS;
        n4 = W_ELEMS / 4;
    }
    int i = blockIdx.x * blockDim.x + threadIdx.x;
    if (i >= n4) return;
    float4 v = reinterpret_cast<const float4*>(src)[i];
    __nv_bfloat16 hx = __float2bfloat16(v.x);
    __nv_bfloat16 hy = __float2bfloat16(v.y);
    __nv_bfloat16 hz = __float2bfloat16(v.z);
    __nv_bfloat16 hw = __float2bfloat16(v.w);
    __nv_bfloat162* hp = reinterpret_cast<__nv_bfloat162*>(hi) + 2 * i;
    hp[0] = __nv_bfloat162(hx, hy);
    hp[1] = __nv_bfloat162(hz, hw);
    __nv_bfloat162* lp = reinterpret_cast<__nv_bfloat162*>(lo) + 2 * i;
    lp[0] = __nv_bfloat162(__float2bfloat16(v.x - __bfloat162float(hx)),
                           __float2bfloat16(v.y - __bfloat162float(hy)));
    lp[1] = __nv_bfloat162(__float2bfloat16(v.z - __bfloat162float(hz)),
                           __float2bfloat16(v.w - __bfloat162float(hw)));
}

// ===========================================================================
// Shared 64x128 GEMM machinery: BM=64, BN=128, BK=32, 256 thr, 8 warps
// 2(M)x4(N), warp tile 32x32. Three-pass MMA order (hh, lh, hl).
// Stage: AH|AL (64x40 bf16) + BH|BL (32x136 bf16) = 27648 B; 2 stages.
// ===========================================================================
#define BK2 32
#define LDA2 40
#define LDB2 136
#define NCH2 (D_MODEL / BK2)         // 24
#define GO_AH 0
#define GO_AL 5120
#define GO_BH 10240
#define GO_BL 18944
#define GO_STAGE 27648
#define SM_GO_TOTAL (2 * GO_STAGE)   // 55296

__device__ __forceinline__ void gemm64_issue_loads(
    uint32_t sb, uint32_t stg, int tid, int m0, int n0, int k0,
    const __nv_bfloat16* Ah, const __nv_bfloat16* Al,
    const __nv_bfloat16* Bh, const __nv_bfloat16* Bl)
{
    // A: 64 rows x 32 k -> 256 uint4; 1 per thread
    {
        const int r = tid >> 2, c8 = (tid & 3) * 8;
        const size_t g = (size_t)(m0 + r) * D_MODEL + k0 + c8;
        const uint32_t so = (uint32_t)(r * LDA2 + c8) * 2;
        cp_async16(sb + stg + GO_AH + so, &Ah[g]);
        cp_async16(sb + stg + GO_AL + so, &Al[g]);
    }
    // B: 32 k x 128 n -> 512 uint4; 2 per thread
#pragma unroll
    for (int it = 0; it < 2; it++) {
        const int idx = tid + it * 256;
        const int r = idx >> 4, n8 = (idx & 15) * 8;
        const size_t g = (size_t)(k0 + r) * D_MODEL + n0 + n8;
        const uint32_t so = (uint32_t)(r * LDB2 + n8) * 2;
        cp_async16(sb + stg + GO_BH + so, &Bh[g]);
        cp_async16(sb + stg + GO_BL + so, &Bl[g]);
    }
}

__device__ __forceinline__ void gemm64_compute_chunk(
    uint32_t sb, uint32_t cur, int lane, int wm, int wn, float c[2][4][4])
{
    const int a_row = lane & 15;
    const int a_kc  = (lane >> 4) * 8;
    const int b_k   = lane & 15;
    const int b_n   = (lane >> 4) * 8;
#pragma unroll
    for (int ks = 0; ks < BK2 / 16; ks++) {
        uint32_t ah0[4], ah1[4], al0[4], al1[4];
        {
            const uint32_t offH = cur + GO_AH +
                ((wm * 32 + a_row) * LDA2 + ks * 16 + a_kc) * 2;
            ldsm_x4(ah0, sb + offH);
            ldsm_x4(ah1, sb + offH + 16 * LDA2 * 2);
            const uint32_t offL = cur + GO_AL +
                ((wm * 32 + a_row) * LDA2 + ks * 16 + a_kc) * 2;
            ldsm_x4(al0, sb + offL);
            ldsm_x4(al1, sb + offL + 16 * LDA2 * 2);
        }
        uint32_t bh[2][4];
#pragma unroll
        for (int nb = 0; nb < 2; nb++) {
            const uint32_t offB = cur + GO_BH +
                ((ks * 16 + b_k) * LDB2 + wn * 32 + nb * 16 + b_n) * 2;
            ldsm_x4_t(bh[nb], sb + offB);
        }
        // Pass 1: hi*hi — 8 distinct accumulators
#pragma unroll
        for (int nb = 0; nb < 2; nb++) {
            mma_bf16(c[0][2 * nb],     ah0, bh[nb][0], bh[nb][1]);
            mma_bf16(c[1][2 * nb],     ah1, bh[nb][0], bh[nb][1]);
            mma_bf16(c[0][2 * nb + 1], ah0, bh[nb][2], bh[nb][3]);
            mma_bf16(c[1][2 * nb + 1], ah1, bh[nb][2], bh[nb][3]);
        }
        // Pass 2: lo*hi
#pragma unroll
        for (int nb = 0; nb < 2; nb++) {
            mma_bf16(c[0][2 * nb],     al0, bh[nb][0], bh[nb][1]);
            mma_bf16(c[1][2 * nb],     al1, bh[nb][0], bh[nb][1]);
            mma_bf16(c[0][2 * nb + 1], al0, bh[nb][2], bh[nb][3]);
            mma_bf16(c[1][2 * nb + 1], al1, bh[nb][2], bh[nb][3]);
        }
        // Pass 3: hi*lo (lazy B-lo loads)
#pragma unroll
        for (int nb = 0; nb < 2; nb++) {
            uint32_t bl[4];
            const uint32_t offB = cur + GO_BL +
                ((ks * 16 + b_k) * LDB2 + wn * 32 + nb * 16 + b_n) * 2;
            ldsm_x4_t(bl, sb + offB);
            mma_bf16(c[0][2 * nb],     ah0, bl[0], bl[1]);
            mma_bf16(c[1][2 * nb],     ah1, bl[0], bl[1]);
            mma_bf16(c[0][2 * nb + 1], ah0, bl[2], bl[3]);
            mma_bf16(c[1][2 * nb + 1], ah1, bl[2], bl[3]);
        }
    }
}

// ===========================================================================
// Fused QKV GEMM (64x128 tiles): blockIdx.z selects {Wq(*ALPHA_Q), Wk, Wv}.
// Grid 64 x 6 x 3 = 1152 CTAs -> 1.95 waves at 2 CTA/SM (97% fill).
// ===========================================================================
__global__ __launch_bounds__(256, 2) void gemm_qkv_kernel(
    const __nv_bfloat16* __restrict__ Ah, const __nv_bfloat16* __restrict__ Al,
    const __nv_bfloat16* __restrict__ whb, const __nv_bfloat16* __restrict__ wlb,
    const float* __restrict__ bq, const float* __restrict__ bk,
    const float* __restrict__ bv,
    __nv_bfloat16* __restrict__ qh, __nv_bfloat16* __restrict__ ql,
    __nv_bfloat16* __restrict__ kh, __nv_bfloat16* __restrict__ kl,
    __nv_bfloat16* __restrict__ vh, __nv_bfloat16* __restrict__ vl)
{
    extern __shared__ char smg[];
    const uint32_t sb = smem_to_u32(smg);
    const int tid  = threadIdx.x;
    const int lane = tid & 31;
    const int w    = tid >> 5;
    const int wm   = w & 1;          // 2 M-warps
    const int wn   = w >> 1;         // 4 N-warps
    const int m0   = blockIdx.x * 64;
    const int n0   = blockIdx.y * 128;
    const int z    = blockIdx.z;

    const __nv_bfloat16* Bh = whb + (size_t)z * W_ELEMS;
    const __nv_bfloat16* Bl = wlb + (size_t)z * W_ELEMS;
    const float* bias = (z == 0) ? bq : (z == 1) ? bk : bv;
    const float alpha = (z == 0) ? ALPHA_Q : 1.0f;
    __nv_bfloat16* Ch = (z == 0) ? qh : (z == 1) ? kh : vh;
    __nv_bfloat16* Cl = (z == 0) ? ql : (z == 1) ? kl : vl;

    float c[2][4][4];
#pragma unroll
    for (int mt = 0; mt < 2; mt++)
#pragma unroll
        for (int nt = 0; nt < 4; nt++)
#pragma unroll
            for (int j = 0; j < 4; j++) c[mt][nt][j] = 0.0f;

    gemm64_issue_loads(sb, 0, tid, m0, n0, 0, Ah, Al, Bh, Bl);
    CP_COMMIT();

    for (int ch = 0; ch < NCH2; ch++) {
        const uint32_t cur = (ch & 1) * GO_STAGE;
        if (ch + 1 < NCH2) {
            gemm64_issue_loads(sb, cur ^ GO_STAGE, tid, m0, n0,
                               (ch + 1) * BK2, Ah, Al, Bh, Bl);
            CP_COMMIT();
            CP_WAIT1();
        } else {
            CP_WAIT0();
        }
        __syncthreads();
        gemm64_compute_chunk(sb, cur, lane, wm, wn, c);
        __syncthreads();
    }

#pragma unroll
    for (int mt = 0; mt < 2; mt++) {
        const int mrow = m0 + wm * 32 + mt * 16 + (lane >> 2);
#pragma unroll
        for (int nt = 0; nt < 4; nt++) {
            const int ncol = n0 + wn * 32 + nt * 8 + (lane & 3) * 2;
            const float b0 = bias[ncol], b1 = bias[ncol + 1];
            const float v00 = alpha * (c[mt][nt][0] + b0);
            const float v01 = alpha * (c[mt][nt][1] + b1);
            const float v10 = alpha * (c[mt][nt][2] + b0);
            const float v11 = alpha * (c[mt][nt][3] + b1);
            const size_t g0 = (size_t)mrow * D_MODEL + ncol;
            const size_t g1 = (size_t)(mrow + 8) * D_MODEL + ncol;
            *reinterpret_cast<uint32_t*>(&Ch[g0]) = cvt_bf16x2(v00, v01);
            *reinterpret_cast<uint32_t*>(&Ch[g1]) = cvt_bf16x2(v10, v11);
            *reinterpret_cast<uint32_t*>(&Cl[g0]) =
                cvt_bf16x2(v00 - bf16_rt(v00), v01 - bf16_rt(v01));
            *reinterpret_cast<uint32_t*>(&Cl[g1]) =
                cvt_bf16x2(v10 - bf16_rt(v10), v11 - bf16_rt(v11));
        }
    }
}

// ===========================================================================
// O-projection GEMM (64x128, fp32 out) — identical mainloop.
// ===========================================================================
__global__ __launch_bounds__(256, 2) void gemm_o_kernel(
    const __nv_bfloat16* __restrict__ Ah, const __nv_bfloat16* __restrict__ Al,
    const __nv_bfloat16* __restrict__ Bh, const __nv_bfloat16* __restrict__ Bl,
    const float* __restrict__ bias, float* __restrict__ Cf)
{
    extern __shared__ char smg[];
    const uint32_t sb = smem_to_u32(smg);
    const int tid  = threadIdx.x;
    const int lane = tid & 31;
    const int w    = tid >> 5;
    const int wm   = w & 1;
    const int wn   = w >> 1;
    const int m0   = blockIdx.x * 64;
    const int n0   = blockIdx.y * 128;

    float c[2][4][4];
#pragma unroll
    for (int mt = 0; mt < 2; mt++)
#pragma unroll
        for (int nt = 0; nt < 4; nt++)
#pragma unroll
            for (int j = 0; j < 4; j++) c[mt][nt][j] = 0.0f;

    gemm64_issue_loads(sb, 0, tid, m0, n0, 0, Ah, Al, Bh, Bl);
    CP_COMMIT();

    for (int ch = 0; ch < NCH2; ch++) {
        const uint32_t cur = (ch & 1) * GO_STAGE;
        if (ch + 1 < NCH2) {
            gemm64_issue_loads(sb, cur ^ GO_STAGE, tid, m0, n0,
                               (ch + 1) * BK2, Ah, Al, Bh, Bl);
            CP_COMMIT();
            CP_WAIT1();
        } else {
            CP_WAIT0();
        }
        __syncthreads();
        gemm64_compute_chunk(sb, cur, lane, wm, wn, c);
        __syncthreads();
    }

#pragma unroll
    for (int mt = 0; mt < 2; mt++) {
        const int mrow = m0 + wm * 32 + mt * 16 + (lane >> 2);
#pragma unroll
        for (int nt = 0; nt < 4; nt++) {
            const int ncol = n0 + wn * 32 + nt * 8 + (lane & 3) * 2;
            const float b0 = bias[ncol], b1 = bias[ncol + 1];
            float2 o0 = make_float2(c[mt][nt][0] + b0, c[mt][nt][1] + b1);
            float2 o1 = make_float2(c[mt][nt][2] + b0, c[mt][nt][3] + b1);
            *reinterpret_cast<float2*>(&Cf[(size_t)mrow * D_MODEL + ncol]) = o0;
            *reinterpret_cast<float2*>(&Cf[(size_t)(mrow + 8) * D_MODEL + ncol]) = o1;
        }
    }
}

// ===========================================================================
// HMMA flash attention (R9 config): BQ=128, 256 thr, 2-stage cp.async,
// exp2-domain softmax. smem: Q 36864 + 2 x 36864 = 110592 B.
// ===========================================================================
#define AT_LD 72
#define A_QH 0
#define A_QL 18432
#define A_QSZ 36864
#define A_KH 0
#define A_KL 9216
#define A_VH 18432
#define A_VL 27648
#define A_STAGE 36864
#define A_SM_TOTAL (A_QSZ + 2 * A_STAGE)   // 110592

__device__ __forceinline__ void attn_issue_loads(
    uint32_t sb, uint32_t stg, int tid, size_t rbase, int kt, int hcol,
    const __nv_bfloat16* Kh, const __nv_bfloat16* Kl,
    const __nv_bfloat16* Vh, const __nv_bfloat16* Vl)
{
    const int r  = tid >> 3;
    const int c8 = (tid & 7) * 8;
#pragma unroll
    for (int it = 0; it < 2; it++) {
        const int rr = r + it * 32;
        const size_t g = (rbase + kt + rr) * D_MODEL + hcol + c8;
        const uint32_t so = (uint32_t)(rr * AT_LD + c8) * 2;
        cp_async16(sb + stg + A_KH + so, &Kh[g]);
        cp_async16(sb + stg + A_KL + so, &Kl[g]);
        cp_async16(sb + stg + A_VH + so, &Vh[g]);
        cp_async16(sb + stg + A_VL + so, &Vl[g]);
    }
}

__global__ __launch_bounds__(256, 2) void attn_hmma_kernel(
    const __nv_bfloat16* __restrict__ Qh, const __nv_bfloat16* __restrict__ Ql,
    const __nv_bfloat16* __restrict__ Kh, const __nv_bfloat16* __restrict__ Kl,
    const __nv_bfloat16* __restrict__ Vh, const __nv_bfloat16* __restrict__ Vl,
    __nv_bfloat16* __restrict__ Ch, __nv_bfloat16* __restrict__ Cl)
{
    extern __shared__ char sma[];
    const uint32_t sb = smem_to_u32(sma);
    const int tid  = threadIdx.x;
    const int lane = tid & 31;
    const int w    = tid >> 5;
    const int q0   = blockIdx.x * 128;
    const int h    = blockIdx.y;
    const int b    = blockIdx.z;
    const int hcol = h * HD;
    const size_t rbase = (size_t)b * S_LEN;

    const int l_row = lane & 15;
    const int l_c8  = (lane >> 4) * 8;

    attn_issue_loads(sb, A_QSZ, tid, rbase, 0, hcol, Kh, Kl, Vh, Vl);
    CP_COMMIT();

    {
        const int r = tid >> 3;
        const int c8 = (tid & 7) * 8;
#pragma unroll
        for (int it = 0; it < 4; it++) {
            const int rr = r + it * 32;
            const size_t g = (rbase + q0 + rr) * D_MODEL + hcol + c8;
            *reinterpret_cast<uint4*>(sma + A_QH + (rr * AT_LD + c8) * 2) =
                *reinterpret_cast<const uint4*>(&Qh[g]);
            *reinterpret_cast<uint4*>(sma + A_QL + (rr * AT_LD + c8) * 2) =
                *reinterpret_cast<const uint4*>(&Ql[g]);
        }
    }

    float ctx[8][4];
#pragma unroll
    for (int nt = 0; nt < 8; nt++)
#pragma unroll
        for (int j = 0; j < 4; j++) ctx[nt][j] = 0.0f;
    float m0r = -INFINITY, m1r = -INFINITY, l0r = 0.0f, l1r = 0.0f;

    const int NT = S_LEN / 64;
    for (int ti = 0; ti < NT; ti++) {
        const uint32_t cur = A_QSZ + (ti & 1) * A_STAGE;
        if (ti + 1 < NT) {
            attn_issue_loads(sb, A_QSZ + ((ti + 1) & 1) * A_STAGE,
                             tid, rbase, (ti + 1) * 64, hcol, Kh, Kl, Vh, Vl);
            CP_COMMIT();
            CP_WAIT1();
        } else {
            CP_WAIT0();
        }
        __syncthreads();

        // ---- S = Q K^T, 3-term split
        float S[8][4];
#pragma unroll
        for (int nt = 0; nt < 8; nt++)
#pragma unroll
            for (int j = 0; j < 4; j++) S[nt][j] = 0.0f;

#pragma unroll
        for (int ks = 0; ks < 4; ks++) {
            uint32_t qh[4], ql[4];
            const uint32_t qoff = ((w * 16 + l_row) * AT_LD + ks * 16 + l_c8) * 2;
            ldsm_x4(qh, sb + A_QH + qoff);
            ldsm_x4(ql, sb + A_QL + qoff);
#pragma unroll
            for (int g = 0; g < 4; g++) {
                uint32_t kh[4], kl[4];
                const uint32_t koff = cur + A_KH +
                    ((g * 16 + l_row) * AT_LD + ks * 16 + l_c8) * 2;
                ldsm_x4(kh, sb + koff);
                ldsm_x4(kl, sb + koff + (A_KL - A_KH));
                mma_bf16(S[2 * g],     qh, kh[0], kh[2]);
                mma_bf16(S[2 * g + 1], qh, kh[1], kh[3]);
                mma_bf16(S[2 * g],     ql, kh[0], kh[2]);
                mma_bf16(S[2 * g + 1], ql, kh[1], kh[3]);
                mma_bf16(S[2 * g],     qh, kl[0], kl[2]);
                mma_bf16(S[2 * g + 1], qh, kl[1], kl[3]);
            }
        }

        // ---- online softmax (exp2 domain)
        float mx0 = -INFINITY, mx1 = -INFINITY;
#pragma unroll
        for (int nt = 0; nt < 8; nt++) {
            mx0 = fmaxf(mx0, fmaxf(S[nt][0], S[nt][1]));
            mx1 = fmaxf(mx1, fmaxf(S[nt][2], S[nt][3]));
        }
        mx0 = fmaxf(mx0, __shfl_xor_sync(0xffffffffu, mx0, 1));
        mx0 = fmaxf(mx0, __shfl_xor_sync(0xffffffffu, mx0, 2));
        mx1 = fmaxf(mx1, __shfl_xor_sync(0xffffffffu, mx1, 1));
        mx1 = fmaxf(mx1, __shfl_xor_sync(0xffffffffu, mx1, 2));
        const float mn0 = fmaxf(m0r, mx0);
        const float mn1 = fmaxf(m1r, mx1);
        const float cr0 = exp2f(m0r - mn0);
        const float cr1 = exp2f(m1r - mn1);
        float s0 = 0.0f, s1 = 0.0f;
#pragma unroll
        for (int nt = 0; nt < 8; nt++) {
            S[nt][0] = exp2f(S[nt][0] - mn0);
            S[nt][1] = exp2f(S[nt][1] - mn0);
            S[nt][2] = exp2f(S[nt][2] - mn1);
            S[nt][3] = exp2f(S[nt][3] - mn1);
            s0 += S[nt][0] + S[nt][1];
            s1 += S[nt][2] + S[nt][3];
            ctx[nt][0] *= cr0; ctx[nt][1] *= cr0;
            ctx[nt][2] *= cr1; ctx[nt][3] *= cr1;
        }
        s0 += __shfl_xor_sync(0xffffffffu, s0, 1);
        s0 += __shfl_xor_sync(0xffffffffu, s0, 2);
        s1 += __shfl_xor_sync(0xffffffffu, s1, 1);
        s1 += __shfl_xor_sync(0xffffffffu, s1, 2);
        l0r = l0r * cr0 + s0;
        l1r = l1r * cr1 + s1;
        m0r = mn0;
        m1r = mn1;

        // ---- pack P into a-frags (hi + lo)
        uint32_t ph[4][4], pl[4][4];
#pragma unroll
        for (int j = 0; j < 4; j++) {
            const float p0 = S[2 * j][0],     p1 = S[2 * j][1];
            const float p2 = S[2 * j][2],     p3 = S[2 * j][3];
            const float p4 = S[2 * j + 1][0], p5 = S[2 * j + 1][1];
            const float p6 = S[2 * j + 1][2], p7 = S[2 * j + 1][3];
            ph[j][0] = cvt_bf16x2(p0, p1);
            ph[j][1] = cvt_bf16x2(p2, p3);
            ph[j][2] = cvt_bf16x2(p4, p5);
            ph[j][3] = cvt_bf16x2(p6, p7);
            pl[j][0] = cvt_bf16x2(p0 - bf16_rt(p0), p1 - bf16_rt(p1));
            pl[j][1] = cvt_bf16x2(p2 - bf16_rt(p2), p3 - bf16_rt(p3));
            pl[j][2] = cvt_bf16x2(p4 - bf16_rt(p4), p5 - bf16_rt(p5));
            pl[j][3] = cvt_bf16x2(p6 - bf16_rt(p6), p7 - bf16_rt(p7));
        }

        // ---- ctx += P V
#pragma unroll
        for (int kc = 0; kc < 4; kc++) {
#pragma unroll
            for (int dg = 0; dg < 4; dg++) {
                uint32_t vh[4], vl[4];
                const uint32_t voff = cur + A_VH +
                    ((kc * 16 + l_row) * AT_LD + dg * 16 + l_c8) * 2;
                ldsm_x4_t(vh, sb + voff);
                ldsm_x4_t(vl, sb + voff + (A_VL - A_VH));
                mma_bf16(ctx[2 * dg],     ph[kc], vh[0], vh[1]);
                mma_bf16(ctx[2 * dg + 1], ph[kc], vh[2], vh[3]);
                mma_bf16(ctx[2 * dg],     pl[kc], vh[0], vh[1]);
                mma_bf16(ctx[2 * dg + 1], pl[kc], vh[2], vh[3]);
                mma_bf16(ctx[2 * dg],     ph[kc], vl[0], vl[1]);
                mma_bf16(ctx[2 * dg + 1], ph[kc], vl[2], vl[3]);
            }
        }
        __syncthreads();
    }

    // ---- epilogue
    const float inv0 = 1.0f / l0r;
    const float inv1 = 1.0f / l1r;
    const int row0 = q0 + w * 16 + (lane >> 2);
#pragma unroll
    for (int nt = 0; nt < 8; nt++) {
        const int col = hcol + nt * 8 + (lane & 3) * 2;
        const float v00 = ctx[nt][0] * inv0, v01 = ctx[nt][1] * inv0;
        const float v10 = ctx[nt][2] * inv1, v11 = ctx[nt][3] * inv1;
        const size_t g0 = (rbase + row0) * D_MODEL + col;
        const size_t g1 = (rbase + row0 + 8) * D_MODEL + col;
        *reinterpret_cast<uint32_t*>(&Ch[g0]) = cvt_bf16x2(v00, v01);
        *reinterpret_cast<uint32_t*>(&Ch[g1]) = cvt_bf16x2(v10, v11);
        *reinterpret_cast<uint32_t*>(&Cl[g0]) =
            cvt_bf16x2(v00 - bf16_rt(v00), v01 - bf16_rt(v01));
        *reinterpret_cast<uint32_t*>(&Cl[g1]) =
            cvt_bf16x2(v10 - bf16_rt(v10), v11 - bf16_rt(v11));
    }
}

// ---------------------------------------------------------------------------
// Launch
// ---------------------------------------------------------------------------
extern "C" void kernel_launch(void* const* d_in, const int* in_sizes, int n_in,
                              void* d_out, int out_size)
{
    const float* x  = (const float*)d_in[0];
    const float* Wq = (const float*)d_in[1];
    const float* bq = (const float*)d_in[2];
    const float* Wk = (const float*)d_in[3];
    const float* bk = (const float*)d_in[4];
    const float* Wv = (const float*)d_in[5];
    const float* bv = (const float*)d_in[6];
    const float* Wo = (const float*)d_in[7];
    const float* bo = (const float*)d_in[8];
    float* out = (float*)d_out;

    __nv_bfloat16 *xh, *xl, *wh, *wl, *qh, *ql, *kh, *kl, *vh, *vl, *ch, *cl;
    cudaGetSymbolAddress((void**)&xh, g_xh);
    cudaGetSymbolAddress((void**)&xl, g_xl);
    cudaGetSymbolAddress((void**)&wh, g_wh);
    cudaGetSymbolAddress((void**)&wl, g_wl);
    cudaGetSymbolAddress((void**)&qh, g_qh);
    cudaGetSymbolAddress((void**)&ql, g_ql);
    cudaGetSymbolAddress((void**)&kh, g_kh);
    cudaGetSymbolAddress((void**)&kl, g_kl);
    cudaGetSymbolAddress((void**)&vh, g_vh);
    cudaGetSymbolAddress((void**)&vl, g_vl);
    cudaGetSymbolAddress((void**)&ch, g_ch);
    cudaGetSymbolAddress((void**)&cl, g_cl);

    cudaFuncSetAttribute(gemm_qkv_kernel,
                         cudaFuncAttributeMaxDynamicSharedMemorySize,
                         SM_GO_TOTAL);
    cudaFuncSetAttribute(gemm_o_kernel,
                         cudaFuncAttributeMaxDynamicSharedMemorySize,
                         SM_GO_TOTAL);
    cudaFuncSetAttribute(attn_hmma_kernel,
                         cudaFuncAttributeMaxDynamicSharedMemorySize,
                         A_SM_TOTAL);

    dim3 split_grid((M_ROWS * D_MODEL / 4 + 255) / 256, 5);
    split_all_kernel<<<split_grid, 256>>>(x, Wq, Wk, Wv, Wo, xh, xl, wh, wl);

    dim3 qkv_grid(M_ROWS / 64, D_MODEL / 128, 3);    // 64 x 6 x 3 = 1152
    gemm_qkv_kernel<<<qkv_grid, 256, SM_GO_TOTAL>>>(
        xh, xl, wh, wl, bq, bk, bv, qh, ql, kh, kl, vh, vl);

    dim3 attn_grid(S_LEN / 128, H_NUM, B_SZ);        // 16 x 12 x 2 = 384
    attn_hmma_kernel<<<attn_grid, 256, A_SM_TOTAL>>>(
        qh, ql, kh, kl, vh, vl, ch, cl);

    dim3 o_grid(M_ROWS / 64, D_MODEL / 128);         // 64 x 6 = 384
    gemm_o_kernel<<<o_grid, 256, SM_GO_TOTAL>>>(
        ch, cl, wh + 3 * W_ELEMS, wl + 3 * W_ELEMS, bo, out);
}

// round 13
// speedup vs baseline: 1.5115x; 1.5115x over previous
#include <cuda_runtime.h>
#include <cuda_fp16.h>
#include <cstdint>
#include <math.h>

// Problem constants
#define S_LEN   2048
#define D_MODEL 768
#define H_NUM   12
#define HD      64
#define B_SZ    2
#define M_ROWS  (B_SZ * S_LEN)   // 4096
#define W_ELEMS (D_MODEL * D_MODEL)

// Q pre-scale: 1/sqrt(64) * log2(e)  (softmax done in exp2 domain)
#define ALPHA_Q (0.125f * 1.44269504088896f)

// Scratch (allocation-free rule: __device__ globals). fp16.
// A-side tensors (x, q, ctx) keep hi/lo; B-side (W, k, v) single fp16.
__device__ __half g_xh[M_ROWS * D_MODEL];
__device__ __half g_xl[M_ROWS * D_MODEL];
__device__ __half g_wh[4 * W_ELEMS];
__device__ __half g_qh[M_ROWS * D_MODEL];
__device__ __half g_ql[M_ROWS * D_MODEL];
__device__ __half g_kh[M_ROWS * D_MODEL];
__device__ __half g_vh[M_ROWS * D_MODEL];
__device__ __half g_ch[M_ROWS * D_MODEL];
__device__ __half g_cl[M_ROWS * D_MODEL];

// ===========================================================================
// Warp-MMA + async-copy helpers
// ===========================================================================
__device__ __forceinline__ uint32_t smem_to_u32(const void* p) {
    uint32_t a;
    asm("{ .reg .u64 t; cvta.to.shared.u64 t, %1; cvt.u32.u64 %0, t; }"
        : "=r"(a) : "l"(p));
    return a;
}
__device__ __forceinline__ void ldsm_x4(uint32_t* r, uint32_t addr) {
    asm volatile(
        "ldmatrix.sync.aligned.m8n8.x4.shared.b16 {%0,%1,%2,%3}, [%4];"
        : "=r"(r[0]), "=r"(r[1]), "=r"(r[2]), "=r"(r[3]) : "r"(addr));
}
__device__ __forceinline__ void ldsm_x4_t(uint32_t* r, uint32_t addr) {
    asm volatile(
        "ldmatrix.sync.aligned.m8n8.x4.trans.shared.b16 {%0,%1,%2,%3}, [%4];"
        : "=r"(r[0]), "=r"(r[1]), "=r"(r[2]), "=r"(r[3]) : "r"(addr));
}
__device__ __forceinline__ void mma_f16(float* c, const uint32_t* a,
                                        uint32_t b0, uint32_t b1) {
    asm volatile(
        "mma.sync.aligned.m16n8k16.row.col.f32.f16.f16.f32 "
        "{%0,%1,%2,%3}, {%4,%5,%6,%7}, {%8,%9}, {%0,%1,%2,%3};"
        : "+f"(c[0]), "+f"(c[1]), "+f"(c[2]), "+f"(c[3])
        : "r"(a[0]), "r"(a[1]), "r"(a[2]), "r"(a[3]), "r"(b0), "r"(b1));
}
// pack two floats into f16x2; first arg = lower-address element
__device__ __forceinline__ uint32_t cvt_f16x2(float lo, float hi) {
    uint32_t r;
    asm("cvt.rn.f16x2.f32 %0, %1, %2;" : "=r"(r) : "f"(hi), "f"(lo));
    return r;
}
__device__ __forceinline__ float h_rt(float x) {
    return __half2float(__float2half_rn(x));
}
__device__ __forceinline__ void cp_async16(uint32_t dst, const void* src) {
    asm volatile("cp.async.cg.shared.global [%0], [%1], 16;"
                 :: "r"(dst), "l"(src) : "memory");
}
#define CP_COMMIT() asm volatile("cp.async.commit_group;" ::: "memory")
#define CP_WAIT1()  asm volatile("cp.async.wait_group 1;" ::: "memory")
#define CP_WAIT0()  asm volatile("cp.async.wait_group 0;" ::: "memory")

// ===========================================================================
// Fused split: x -> (fp16 hi, fp16 lo); weights -> fp16 hi only.
// ===========================================================================
__global__ __launch_bounds__(256) void split_all_kernel(
    const float* __restrict__ x,
    const float* __restrict__ Wq, const float* __restrict__ Wk,
    const float* __restrict__ Wv, const float* __restrict__ Wo,
    __half* __restrict__ xh, __half* __restrict__ xl,
    __half* __restrict__ wh)
{
    const int t = blockIdx.y;
    const float* src;
    __half *hi, *lo = nullptr;
    int n4;
    if (t == 0) { src = x;  hi = xh; lo = xl; n4 = M_ROWS * D_MODEL / 4; }
    else {
        const float* ws[4] = {Wq, Wk, Wv, Wo};
        src = ws[t - 1];
        hi = wh + (size_t)(t - 1) * W_ELEMS;
        n4 = W_ELEMS / 4;
    }
    int i = blockIdx.x * blockDim.x + threadIdx.x;
    if (i >= n4) return;
    float4 v = reinterpret_cast<const float4*>(src)[i];
    uint32_t* hp = reinterpret_cast<uint32_t*>(hi) + 2 * i;
    hp[0] = cvt_f16x2(v.x, v.y);
    hp[1] = cvt_f16x2(v.z, v.w);
    if (lo) {
        uint32_t* lp = reinterpret_cast<uint32_t*>(lo) + 2 * i;
        lp[0] = cvt_f16x2(v.x - h_rt(v.x), v.y - h_rt(v.y));
        lp[1] = cvt_f16x2(v.z - h_rt(v.z), v.w - h_rt(v.w));
    }
}

// ===========================================================================
// QKV GEMM: CTA tile 128x128, BK=32, 256 thr, 8 warps 4(M)x2(N), warp 32x64.
// Two-pass MMA order (hh x16, lh x16). B single fp16.
// Stage: AH|AL (128x40 f16 ea = 10240 B) + BH (32x136 f16 = 8704 B) = 29184 B.
// ===========================================================================
#define BM2 128
#define BN2 128
#define BK2 32
#define LDA2 40
#define LDB2 136
#define G2_AH 0
#define G2_AL 10240
#define G2_BH 20480
#define G2_STAGE 29184
#define SM_G2_TOTAL (2 * G2_STAGE)   // 58368
#define NCH2 (D_MODEL / BK2)         // 24

__device__ __forceinline__ void gemm2_issue_loads(
    uint32_t sb, uint32_t stg, int tid, int m0, int n0, int k0,
    const __half* Ah, const __half* Al, const __half* Bh)
{
#pragma unroll
    for (int it = 0; it < 2; it++) {
        const int idx = tid + it * 256;
        // A: 128 rows x 32 k -> 512 uint4
        {
            const int r = idx >> 2, c8 = (idx & 3) * 8;
            const size_t g = (size_t)(m0 + r) * D_MODEL + k0 + c8;
            const uint32_t so = (uint32_t)(r * LDA2 + c8) * 2;
            cp_async16(sb + stg + G2_AH + so, &Ah[g]);
            cp_async16(sb + stg + G2_AL + so, &Al[g]);
        }
        // B: 32 k x 128 n -> 512 uint4
        {
            const int r = idx >> 4, n8 = (idx & 15) * 8;
            const size_t g = (size_t)(k0 + r) * D_MODEL + n0 + n8;
            const uint32_t so = (uint32_t)(r * LDB2 + n8) * 2;
            cp_async16(sb + stg + G2_BH + so, &Bh[g]);
        }
    }
}

__device__ __forceinline__ void gemm2_compute_chunk(
    uint32_t sb, uint32_t stg, int lane, int wm, int wn, float c[2][8][4])
{
    const int a_row = lane & 15;
    const int a_kc  = (lane >> 4) * 8;
    const int b_k   = lane & 15;
    const int b_n   = (lane >> 4) * 8;
#pragma unroll
    for (int ks = 0; ks < BK2 / 16; ks++) {
        uint32_t ah0[4], ah1[4], al0[4], al1[4];
        {
            const uint32_t offH = stg + G2_AH +
                ((wm * 32 + a_row) * LDA2 + ks * 16 + a_kc) * 2;
            ldsm_x4(ah0, sb + offH);
            ldsm_x4(ah1, sb + offH + 16 * LDA2 * 2);
            const uint32_t offL = stg + G2_AL +
                ((wm * 32 + a_row) * LDA2 + ks * 16 + a_kc) * 2;
            ldsm_x4(al0, sb + offL);
            ldsm_x4(al1, sb + offL + 16 * LDA2 * 2);
        }
        uint32_t bh[4][4];
#pragma unroll
        for (int nb = 0; nb < 4; nb++) {
            const uint32_t offB = stg + G2_BH +
                ((ks * 16 + b_k) * LDB2 + wn * 64 + nb * 16 + b_n) * 2;
            ldsm_x4_t(bh[nb], sb + offB);
        }
        // Pass 1: hi*hi — 16 MMAs, distinct accumulators
#pragma unroll
        for (int nb = 0; nb < 4; nb++) {
            mma_f16(c[0][2 * nb],     ah0, bh[nb][0], bh[nb][1]);
            mma_f16(c[1][2 * nb],     ah1, bh[nb][0], bh[nb][1]);
            mma_f16(c[0][2 * nb + 1], ah0, bh[nb][2], bh[nb][3]);
            mma_f16(c[1][2 * nb + 1], ah1, bh[nb][2], bh[nb][3]);
        }
        // Pass 2: lo*hi — 16 MMAs
#pragma unroll
        for (int nb = 0; nb < 4; nb++) {
            mma_f16(c[0][2 * nb],     al0, bh[nb][0], bh[nb][1]);
            mma_f16(c[1][2 * nb],     al1, bh[nb][0], bh[nb][1]);
            mma_f16(c[0][2 * nb + 1], al0, bh[nb][2], bh[nb][3]);
            mma_f16(c[1][2 * nb + 1], al1, bh[nb][2], bh[nb][3]);
        }
    }
}

// blockIdx.z: 0 -> Q (hi/lo, *ALPHA_Q), 1 -> K (single), 2 -> V (single)
__global__ __launch_bounds__(256, 2) void gemm_qkv_kernel(
    const __half* __restrict__ Ah, const __half* __restrict__ Al,
    const __half* __restrict__ whb,
    const float* __restrict__ bq, const float* __restrict__ bk,
    const float* __restrict__ bv,
    __half* __restrict__ qh, __half* __restrict__ ql,
    __half* __restrict__ kh, __half* __restrict__ vh)
{
    extern __shared__ char smg[];
    const uint32_t sb = smem_to_u32(smg);
    const int tid  = threadIdx.x;
    const int lane = tid & 31;
    const int w    = tid >> 5;
    const int wm   = w & 3;
    const int wn   = w >> 2;
    const int m0   = blockIdx.x * BM2;
    const int n0   = blockIdx.y * BN2;
    const int z    = blockIdx.z;

    const __half* Bh = whb + (size_t)z * W_ELEMS;
    const float* bias = (z == 0) ? bq : (z == 1) ? bk : bv;
    const float alpha = (z == 0) ? ALPHA_Q : 1.0f;
    __half* Ch = (z == 0) ? qh : (z == 1) ? kh : vh;

    float c[2][8][4];
#pragma unroll
    for (int mt = 0; mt < 2; mt++)
#pragma unroll
        for (int nt = 0; nt < 8; nt++)
#pragma unroll
            for (int j = 0; j < 4; j++) c[mt][nt][j] = 0.0f;

    gemm2_issue_loads(sb, 0, tid, m0, n0, 0, Ah, Al, Bh);
    CP_COMMIT();

    for (int ch = 0; ch < NCH2; ch++) {
        const uint32_t cur = (ch & 1) * G2_STAGE;
        if (ch + 1 < NCH2) {
            gemm2_issue_loads(sb, cur ^ G2_STAGE, tid, m0, n0,
                              (ch + 1) * BK2, Ah, Al, Bh);
            CP_COMMIT();
            CP_WAIT1();
        } else {
            CP_WAIT0();
        }
        __syncthreads();
        gemm2_compute_chunk(sb, cur, lane, wm, wn, c);
        __syncthreads();
    }

#pragma unroll
    for (int mt = 0; mt < 2; mt++) {
        const int mrow = m0 + wm * 32 + mt * 16 + (lane >> 2);
#pragma unroll
        for (int nt = 0; nt < 8; nt++) {
            const int ncol = n0 + wn * 64 + nt * 8 + (lane & 3) * 2;
            const float b0 = bias[ncol], b1 = bias[ncol + 1];
            const float v00 = alpha * (c[mt][nt][0] + b0);
            const float v01 = alpha * (c[mt][nt][1] + b1);
            const float v10 = alpha * (c[mt][nt][2] + b0);
            const float v11 = alpha * (c[mt][nt][3] + b1);
            const size_t g0 = (size_t)mrow * D_MODEL + ncol;
            const size_t g1 = (size_t)(mrow + 8) * D_MODEL + ncol;
            *reinterpret_cast<uint32_t*>(&Ch[g0]) = cvt_f16x2(v00, v01);
            *reinterpret_cast<uint32_t*>(&Ch[g1]) = cvt_f16x2(v10, v11);
            if (z == 0) {
                *reinterpret_cast<uint32_t*>(&ql[g0]) =
                    cvt_f16x2(v00 - h_rt(v00), v01 - h_rt(v01));
                *reinterpret_cast<uint32_t*>(&ql[g1]) =
                    cvt_f16x2(v10 - h_rt(v10), v11 - h_rt(v11));
            }
        }
    }
}

// ===========================================================================
// O-projection GEMM: BM=64 x BN=128, 256 thr, 8 warps 2(M)x4(N), warp 32x32.
// fp32 output. Stage: AH|AL (64x40 ea = 5120) + BH (8704) = 18944 B.
// ===========================================================================
#define GO_AH 0
#define GO_AL 5120
#define GO_BH 10240
#define GO_STAGE 18944
#define SM_GO_TOTAL (2 * GO_STAGE)   // 37888

__device__ __forceinline__ void gemmo_issue_loads(
    uint32_t sb, uint32_t stg, int tid, int m0, int n0, int k0,
    const __half* Ah, const __half* Al, const __half* Bh)
{
    // A: 64 rows x 32 k -> 256 uint4; 1 per thread
    {
        const int r = tid >> 2, c8 = (tid & 3) * 8;
        const size_t g = (size_t)(m0 + r) * D_MODEL + k0 + c8;
        const uint32_t so = (uint32_t)(r * LDA2 + c8) * 2;
        cp_async16(sb + stg + GO_AH + so, &Ah[g]);
        cp_async16(sb + stg + GO_AL + so, &Al[g]);
    }
    // B: 32 k x 128 n -> 512 uint4; 2 per thread
#pragma unroll
    for (int it = 0; it < 2; it++) {
        const int idx = tid + it * 256;
        const int r = idx >> 4, n8 = (idx & 15) * 8;
        const size_t g = (size_t)(k0 + r) * D_MODEL + n0 + n8;
        const uint32_t so = (uint32_t)(r * LDB2 + n8) * 2;
        cp_async16(sb + stg + GO_BH + so, &Bh[g]);
    }
}

__global__ __launch_bounds__(256, 2) void gemm_o_kernel(
    const __half* __restrict__ Ah, const __half* __restrict__ Al,
    const __half* __restrict__ Bh,
    const float* __restrict__ bias, float* __restrict__ Cf)
{
    extern __shared__ char smg[];
    const uint32_t sb = smem_to_u32(smg);
    const int tid  = threadIdx.x;
    const int lane = tid & 31;
    const int w    = tid >> 5;
    const int wm   = w & 1;
    const int wn   = w >> 1;
    const int m0   = blockIdx.x * 64;
    const int n0   = blockIdx.y * 128;

    const int a_row = lane & 15;
    const int a_kc  = (lane >> 4) * 8;
    const int b_k   = lane & 15;
    const int b_n   = (lane >> 4) * 8;

    float c[2][4][4];
#pragma unroll
    for (int mt = 0; mt < 2; mt++)
#pragma unroll
        for (int nt = 0; nt < 4; nt++)
#pragma unroll
            for (int j = 0; j < 4; j++) c[mt][nt][j] = 0.0f;

    gemmo_issue_loads(sb, 0, tid, m0, n0, 0, Ah, Al, Bh);
    CP_COMMIT();

    for (int ch = 0; ch < NCH2; ch++) {
        const uint32_t cur = (ch & 1) * GO_STAGE;
        if (ch + 1 < NCH2) {
            gemmo_issue_loads(sb, cur ^ GO_STAGE, tid, m0, n0,
                              (ch + 1) * BK2, Ah, Al, Bh);
            CP_COMMIT();
            CP_WAIT1();
        } else {
            CP_WAIT0();
        }
        __syncthreads();

#pragma unroll
        for (int ks = 0; ks < BK2 / 16; ks++) {
            uint32_t ah0[4], ah1[4], al0[4], al1[4];
            {
                const uint32_t offH = cur + GO_AH +
                    ((wm * 32 + a_row) * LDA2 + ks * 16 + a_kc) * 2;
                ldsm_x4(ah0, sb + offH);
                ldsm_x4(ah1, sb + offH + 16 * LDA2 * 2);
                const uint32_t offL = cur + GO_AL +
                    ((wm * 32 + a_row) * LDA2 + ks * 16 + a_kc) * 2;
                ldsm_x4(al0, sb + offL);
                ldsm_x4(al1, sb + offL + 16 * LDA2 * 2);
            }
            uint32_t bh[2][4];
#pragma unroll
            for (int nb = 0; nb < 2; nb++) {
                const uint32_t offB = cur + GO_BH +
                    ((ks * 16 + b_k) * LDB2 + wn * 32 + nb * 16 + b_n) * 2;
                ldsm_x4_t(bh[nb], sb + offB);
            }
#pragma unroll
            for (int nb = 0; nb < 2; nb++) {
                mma_f16(c[0][2 * nb],     ah0, bh[nb][0], bh[nb][1]);
                mma_f16(c[1][2 * nb],     ah1, bh[nb][0], bh[nb][1]);
                mma_f16(c[0][2 * nb + 1], ah0, bh[nb][2], bh[nb][3]);
                mma_f16(c[1][2 * nb + 1], ah1, bh[nb][2], bh[nb][3]);
            }
#pragma unroll
            for (int nb = 0; nb < 2; nb++) {
                mma_f16(c[0][2 * nb],     al0, bh[nb][0], bh[nb][1]);
                mma_f16(c[1][2 * nb],     al1, bh[nb][0], bh[nb][1]);
                mma_f16(c[0][2 * nb + 1], al0, bh[nb][2], bh[nb][3]);
                mma_f16(c[1][2 * nb + 1], al1, bh[nb][2], bh[nb][3]);
            }
        }
        __syncthreads();
    }

#pragma unroll
    for (int mt = 0; mt < 2; mt++) {
        const int mrow = m0 + wm * 32 + mt * 16 + (lane >> 2);
#pragma unroll
        for (int nt = 0; nt < 4; nt++) {
            const int ncol = n0 + wn * 32 + nt * 8 + (lane & 3) * 2;
            const float b0 = bias[ncol], b1 = bias[ncol + 1];
            float2 o0 = make_float2(c[mt][nt][0] + b0, c[mt][nt][1] + b1);
            float2 o1 = make_float2(c[mt][nt][2] + b0, c[mt][nt][3] + b1);
            *reinterpret_cast<float2*>(&Cf[(size_t)mrow * D_MODEL + ncol]) = o0;
            *reinterpret_cast<float2*>(&Cf[(size_t)(mrow + 8) * D_MODEL + ncol]) = o1;
        }
    }
}

// ===========================================================================
// fp16 flash attention: BQ=128, 256 thr. Q hi/lo; K,V single fp16.
// S = QhK + QlK; ctx = PhV + PlV. exp2-domain softmax. 2-stage cp.async.
// smem: Q (hi+lo) 36864 + 2 stages x (KH|VH = 18432) = 73728 B.
// ===========================================================================
#define AT_LD 72
#define A_QH 0
#define A_QL 18432
#define A_QSZ 36864
#define A_KH 0
#define A_VH 9216
#define A_STAGE 18432
#define A_SM_TOTAL (A_QSZ + 2 * A_STAGE)   // 73728

__device__ __forceinline__ void attn_issue_loads(
    uint32_t sb, uint32_t stg, int tid, size_t rbase, int kt, int hcol,
    const __half* Kh, const __half* Vh)
{
    const int r  = tid >> 3;
    const int c8 = (tid & 7) * 8;
#pragma unroll
    for (int it = 0; it < 2; it++) {
        const int rr = r + it * 32;
        const size_t g = (rbase + kt + rr) * D_MODEL + hcol + c8;
        const uint32_t so = (uint32_t)(rr * AT_LD + c8) * 2;
        cp_async16(sb + stg + A_KH + so, &Kh[g]);
        cp_async16(sb + stg + A_VH + so, &Vh[g]);
    }
}

__global__ __launch_bounds__(256, 2) void attn_hmma_kernel(
    const __half* __restrict__ Qh, const __half* __restrict__ Ql,
    const __half* __restrict__ Kh, const __half* __restrict__ Vh,
    __half* __restrict__ Ch, __half* __restrict__ Cl)
{
    extern __shared__ char sma[];
    const uint32_t sb = smem_to_u32(sma);
    const int tid  = threadIdx.x;
    const int lane = tid & 31;
    const int w    = tid >> 5;
    const int q0   = blockIdx.x * 128;
    const int h    = blockIdx.y;
    const int b    = blockIdx.z;
    const int hcol = h * HD;
    const size_t rbase = (size_t)b * S_LEN;

    const int l_row = lane & 15;
    const int l_c8  = (lane >> 4) * 8;

    attn_issue_loads(sb, A_QSZ, tid, rbase, 0, hcol, Kh, Vh);
    CP_COMMIT();

    {
        const int r = tid >> 3;
        const int c8 = (tid & 7) * 8;
#pragma unroll
        for (int it = 0; it < 4; it++) {
            const int rr = r + it * 32;
            const size_t g = (rbase + q0 + rr) * D_MODEL + hcol + c8;
            *reinterpret_cast<uint4*>(sma + A_QH + (rr * AT_LD + c8) * 2) =
                *reinterpret_cast<const uint4*>(&Qh[g]);
            *reinterpret_cast<uint4*>(sma + A_QL + (rr * AT_LD + c8) * 2) =
                *reinterpret_cast<const uint4*>(&Ql[g]);
        }
    }

    float ctx[8][4];
#pragma unroll
    for (int nt = 0; nt < 8; nt++)
#pragma unroll
        for (int j = 0; j < 4; j++) ctx[nt][j] = 0.0f;
    float m0r = -INFINITY, m1r = -INFINITY, l0r = 0.0f, l1r = 0.0f;

    const int NT = S_LEN / 64;
    for (int ti = 0; ti < NT; ti++) {
        const uint32_t cur = A_QSZ + (ti & 1) * A_STAGE;
        if (ti + 1 < NT) {
            attn_issue_loads(sb, A_QSZ + ((ti + 1) & 1) * A_STAGE,
                             tid, rbase, (ti + 1) * 64, hcol, Kh, Vh);
            CP_COMMIT();
            CP_WAIT1();
        } else {
            CP_WAIT0();
        }
        __syncthreads();

        // ---- S = Q K^T, 2-term split
        float S[8][4];
#pragma unroll
        for (int nt = 0; nt < 8; nt++)
#pragma unroll
            for (int j = 0; j < 4; j++) S[nt][j] = 0.0f;

#pragma unroll
        for (int ks = 0; ks < 4; ks++) {
            uint32_t qh[4], ql[4];
            const uint32_t qoff = ((w * 16 + l_row) * AT_LD + ks * 16 + l_c8) * 2;
            ldsm_x4(qh, sb + A_QH + qoff);
            ldsm_x4(ql, sb + A_QL + qoff);
#pragma unroll
            for (int g = 0; g < 4; g++) {
                uint32_t kh[4];
                const uint32_t koff = cur + A_KH +
                    ((g * 16 + l_row) * AT_LD + ks * 16 + l_c8) * 2;
                ldsm_x4(kh, sb + koff);
                mma_f16(S[2 * g],     qh, kh[0], kh[2]);
                mma_f16(S[2 * g + 1], qh, kh[1], kh[3]);
                mma_f16(S[2 * g],     ql, kh[0], kh[2]);
                mma_f16(S[2 * g + 1], ql, kh[1], kh[3]);
            }
        }

        // ---- online softmax (exp2 domain)
        float mx0 = -INFINITY, mx1 = -INFINITY;
#pragma unroll
        for (int nt = 0; nt < 8; nt++) {
            mx0 = fmaxf(mx0, fmaxf(S[nt][0], S[nt][1]));
            mx1 = fmaxf(mx1, fmaxf(S[nt][2], S[nt][3]));
        }
        mx0 = fmaxf(mx0, __shfl_xor_sync(0xffffffffu, mx0, 1));
        mx0 = fmaxf(mx0, __shfl_xor_sync(0xffffffffu, mx0, 2));
        mx1 = fmaxf(mx1, __shfl_xor_sync(0xffffffffu, mx1, 1));
        mx1 = fmaxf(mx1, __shfl_xor_sync(0xffffffffu, mx1, 2));
        const float mn0 = fmaxf(m0r, mx0);
        const float mn1 = fmaxf(m1r, mx1);
        const float cr0 = exp2f(m0r - mn0);
        const float cr1 = exp2f(m1r - mn1);
        float s0 = 0.0f, s1 = 0.0f;
#pragma unroll
        for (int nt = 0; nt < 8; nt++) {
            S[nt][0] = exp2f(S[nt][0] - mn0);
            S[nt][1] = exp2f(S[nt][1] - mn0);
            S[nt][2] = exp2f(S[nt][2] - mn1);
            S[nt][3] = exp2f(S[nt][3] - mn1);
            s0 += S[nt][0] + S[nt][1];
            s1 += S[nt][2] + S[nt][3];
            ctx[nt][0] *= cr0; ctx[nt][1] *= cr0;
            ctx[nt][2] *= cr1; ctx[nt][3] *= cr1;
        }
        s0 += __shfl_xor_sync(0xffffffffu, s0, 1);
        s0 += __shfl_xor_sync(0xffffffffu, s0, 2);
        s1 += __shfl_xor_sync(0xffffffffu, s1, 1);
        s1 += __shfl_xor_sync(0xffffffffu, s1, 2);
        l0r = l0r * cr0 + s0;
        l1r = l1r * cr1 + s1;
        m0r = mn0;
        m1r = mn1;

        // ---- pack P into a-frags (hi + lo, fp16)
        uint32_t ph[4][4], pl[4][4];
#pragma unroll
        for (int j = 0; j < 4; j++) {
            const float p0 = S[2 * j][0],     p1 = S[2 * j][1];
            const float p2 = S[2 * j][2],     p3 = S[2 * j][3];
            const float p4 = S[2 * j + 1][0], p5 = S[2 * j + 1][1];
            const float p6 = S[2 * j + 1][2], p7 = S[2 * j + 1][3];
            ph[j][0] = cvt_f16x2(p0, p1);
            ph[j][1] = cvt_f16x2(p2, p3);
            ph[j][2] = cvt_f16x2(p4, p5);
            ph[j][3] = cvt_f16x2(p6, p7);
            pl[j][0] = cvt_f16x2(p0 - h_rt(p0), p1 - h_rt(p1));
            pl[j][1] = cvt_f16x2(p2 - h_rt(p2), p3 - h_rt(p3));
            pl[j][2] = cvt_f16x2(p4 - h_rt(p4), p5 - h_rt(p5));
            pl[j][3] = cvt_f16x2(p6 - h_rt(p6), p7 - h_rt(p7));
        }

        // ---- ctx += P V, 2-term
#pragma unroll
        for (int kc = 0; kc < 4; kc++) {
#pragma unroll
            for (int dg = 0; dg < 4; dg++) {
                uint32_t vh[4];
                const uint32_t voff = cur + A_VH +
                    ((kc * 16 + l_row) * AT_LD + dg * 16 + l_c8) * 2;
                ldsm_x4_t(vh, sb + voff);
                mma_f16(ctx[2 * dg],     ph[kc], vh[0], vh[1]);
                mma_f16(ctx[2 * dg + 1], ph[kc], vh[2], vh[3]);
                mma_f16(ctx[2 * dg],     pl[kc], vh[0], vh[1]);
                mma_f16(ctx[2 * dg + 1], pl[kc], vh[2], vh[3]);
            }
        }
        __syncthreads();
    }

    // ---- epilogue: normalize, split, store ctx hi/lo (fp16)
    const float inv0 = 1.0f / l0r;
    const float inv1 = 1.0f / l1r;
    const int row0 = q0 + w * 16 + (lane >> 2);
#pragma unroll
    for (int nt = 0; nt < 8; nt++) {
        const int col = hcol + nt * 8 + (lane & 3) * 2;
        const float v00 = ctx[nt][0] * inv0, v01 = ctx[nt][1] * inv0;
        const float v10 = ctx[nt][2] * inv1, v11 = ctx[nt][3] * inv1;
        const size_t g0 = (rbase + row0) * D_MODEL + col;
        const size_t g1 = (rbase + row0 + 8) * D_MODEL + col;
        *reinterpret_cast<uint32_t*>(&Ch[g0]) = cvt_f16x2(v00, v01);
        *reinterpret_cast<uint32_t*>(&Ch[g1]) = cvt_f16x2(v10, v11);
        *reinterpret_cast<uint32_t*>(&Cl[g0]) =
            cvt_f16x2(v00 - h_rt(v00), v01 - h_rt(v01));
        *reinterpret_cast<uint32_t*>(&Cl[g1]) =
            cvt_f16x2(v10 - h_rt(v10), v11 - h_rt(v11));
    }
}

// ---------------------------------------------------------------------------
// Launch
// ---------------------------------------------------------------------------
extern "C" void kernel_launch(void* const* d_in, const int* in_sizes, int n_in,
                              void* d_out, int out_size)
{
    const float* x  = (const float*)d_in[0];
    const float* Wq = (const float*)d_in[1];
    const float* bq = (const float*)d_in[2];
    const float* Wk = (const float*)d_in[3];
    const float* bk = (const float*)d_in[4];
    const float* Wv = (const float*)d_in[5];
    const float* bv = (const float*)d_in[6];
    const float* Wo = (const float*)d_in[7];
    const float* bo = (const float*)d_in[8];
    float* out = (float*)d_out;

    __half *xh, *xl, *wh, *qh, *ql, *kh, *vh, *ch, *cl;
    cudaGetSymbolAddress((void**)&xh, g_xh);
    cudaGetSymbolAddress((void**)&xl, g_xl);
    cudaGetSymbolAddress((void**)&wh, g_wh);
    cudaGetSymbolAddress((void**)&qh, g_qh);
    cudaGetSymbolAddress((void**)&ql, g_ql);
    cudaGetSymbolAddress((void**)&kh, g_kh);
    cudaGetSymbolAddress((void**)&vh, g_vh);
    cudaGetSymbolAddress((void**)&ch, g_ch);
    cudaGetSymbolAddress((void**)&cl, g_cl);

    cudaFuncSetAttribute(gemm_qkv_kernel,
                         cudaFuncAttributeMaxDynamicSharedMemorySize,
                         SM_G2_TOTAL);
    cudaFuncSetAttribute(gemm_o_kernel,
                         cudaFuncAttributeMaxDynamicSharedMemorySize,
                         SM_GO_TOTAL);
    cudaFuncSetAttribute(attn_hmma_kernel,
                         cudaFuncAttributeMaxDynamicSharedMemorySize,
                         A_SM_TOTAL);

    dim3 split_grid((M_ROWS * D_MODEL / 4 + 255) / 256, 5);
    split_all_kernel<<<split_grid, 256>>>(x, Wq, Wk, Wv, Wo, xh, xl, wh);

    dim3 qkv_grid(M_ROWS / BM2, D_MODEL / BN2, 3);   // 32 x 6 x 3 = 576
    gemm_qkv_kernel<<<qkv_grid, 256, SM_G2_TOTAL>>>(
        xh, xl, wh, bq, bk, bv, qh, ql, kh, vh);

    dim3 attn_grid(S_LEN / 128, H_NUM, B_SZ);        // 16 x 12 x 2 = 384
    attn_hmma_kernel<<<attn_grid, 256, A_SM_TOTAL>>>(
        qh, ql, kh, vh, ch, cl);

    dim3 o_grid(M_ROWS / 64, D_MODEL / 128);         // 64 x 6 = 384
    gemm_o_kernel<<<o_grid, 256, SM_GO_TOTAL>>>(
        ch, cl, wh + 3 * W_ELEMS, bo, out);
}

// round 14
// speedup vs baseline: 1.5319x; 1.0135x over previous
#include <cuda_runtime.h>
#include <cuda_fp16.h>
#include <cstdint>
#include <math.h>

// Problem constants
#define S_LEN   2048
#define D_MODEL 768
#define H_NUM   12
#define HD      64
#define B_SZ    2
#define M_ROWS  (B_SZ * S_LEN)   // 4096
#define W_ELEMS (D_MODEL * D_MODEL)

// Q pre-scale: 1/sqrt(64) * log2(e)  (softmax done in exp2 domain)
#define ALPHA_Q (0.125f * 1.44269504088896f)

// Scratch (allocation-free rule: __device__ globals). fp16.
// A-side tensors (x, q, ctx) keep hi/lo; B-side (W, k, v) single fp16.
__device__ __half g_xh[M_ROWS * D_MODEL];
__device__ __half g_xl[M_ROWS * D_MODEL];
__device__ __half g_wh[4 * W_ELEMS];
__device__ __half g_qh[M_ROWS * D_MODEL];
__device__ __half g_ql[M_ROWS * D_MODEL];
__device__ __half g_kh[M_ROWS * D_MODEL];
__device__ __half g_vh[M_ROWS * D_MODEL];
__device__ __half g_ch[M_ROWS * D_MODEL];
__device__ __half g_cl[M_ROWS * D_MODEL];

// ===========================================================================
// Warp-MMA + async-copy helpers
// ===========================================================================
__device__ __forceinline__ uint32_t smem_to_u32(const void* p) {
    uint32_t a;
    asm("{ .reg .u64 t; cvta.to.shared.u64 t, %1; cvt.u32.u64 %0, t; }"
        : "=r"(a) : "l"(p));
    return a;
}
__device__ __forceinline__ void ldsm_x4(uint32_t* r, uint32_t addr) {
    asm volatile(
        "ldmatrix.sync.aligned.m8n8.x4.shared.b16 {%0,%1,%2,%3}, [%4];"
        : "=r"(r[0]), "=r"(r[1]), "=r"(r[2]), "=r"(r[3]) : "r"(addr));
}
__device__ __forceinline__ void ldsm_x4_t(uint32_t* r, uint32_t addr) {
    asm volatile(
        "ldmatrix.sync.aligned.m8n8.x4.trans.shared.b16 {%0,%1,%2,%3}, [%4];"
        : "=r"(r[0]), "=r"(r[1]), "=r"(r[2]), "=r"(r[3]) : "r"(addr));
}
__device__ __forceinline__ void mma_f16(float* c, const uint32_t* a,
                                        uint32_t b0, uint32_t b1) {
    asm volatile(
        "mma.sync.aligned.m16n8k16.row.col.f32.f16.f16.f32 "
        "{%0,%1,%2,%3}, {%4,%5,%6,%7}, {%8,%9}, {%0,%1,%2,%3};"
        : "+f"(c[0]), "+f"(c[1]), "+f"(c[2]), "+f"(c[3])
        : "r"(a[0]), "r"(a[1]), "r"(a[2]), "r"(a[3]), "r"(b0), "r"(b1));
}
// pack two floats into f16x2; first arg = lower-address element
__device__ __forceinline__ uint32_t cvt_f16x2(float lo, float hi) {
    uint32_t r;
    asm("cvt.rn.f16x2.f32 %0, %1, %2;" : "=r"(r) : "f"(hi), "f"(lo));
    return r;
}
__device__ __forceinline__ float h_rt(float x) {
    return __half2float(__float2half_rn(x));
}
__device__ __forceinline__ void cp_async16(uint32_t dst, const void* src) {
    asm volatile("cp.async.cg.shared.global [%0], [%1], 16;"
                 :: "r"(dst), "l"(src) : "memory");
}
#define CP_COMMIT() asm volatile("cp.async.commit_group;" ::: "memory")
#define CP_WAIT1()  asm volatile("cp.async.wait_group 1;" ::: "memory")
#define CP_WAIT0()  asm volatile("cp.async.wait_group 0;" ::: "memory")

// ===========================================================================
// Fused split: x -> (fp16 hi, fp16 lo); weights -> fp16 hi only.
// Each thread handles 4 strided float4s (MLP=4; splits were latency-bound).
// ===========================================================================
__global__ __launch_bounds__(256) void split_all_kernel(
    const float* __restrict__ x,
    const float* __restrict__ Wq, const float* __restrict__ Wk,
    const float* __restrict__ Wv, const float* __restrict__ Wo,
    __half* __restrict__ xh, __half* __restrict__ xl,
    __half* __restrict__ wh)
{
    const int t = blockIdx.y;
    const float* src;
    __half *hi, *lo = nullptr;
    int n4;
    if (t == 0) { src = x;  hi = xh; lo = xl; n4 = M_ROWS * D_MODEL / 4; }
    else {
        const float* ws[4] = {Wq, Wk, Wv, Wo};
        src = ws[t - 1];
        hi = wh + (size_t)(t - 1) * W_ELEMS;
        n4 = W_ELEMS / 4;
    }
    const int q = n4 >> 2;   // quarter stride
    const int i0 = blockIdx.x * blockDim.x + threadIdx.x;
    if (i0 >= q) return;
#pragma unroll
    for (int it = 0; it < 4; it++) {
        const int i = i0 + it * q;
        float4 v = reinterpret_cast<const float4*>(src)[i];
        uint32_t* hp = reinterpret_cast<uint32_t*>(hi) + 2 * i;
        hp[0] = cvt_f16x2(v.x, v.y);
        hp[1] = cvt_f16x2(v.z, v.w);
        if (lo) {
            uint32_t* lp = reinterpret_cast<uint32_t*>(lo) + 2 * i;
            lp[0] = cvt_f16x2(v.x - h_rt(v.x), v.y - h_rt(v.y));
            lp[1] = cvt_f16x2(v.z - h_rt(v.z), v.w - h_rt(v.w));
        }
    }
}

// ===========================================================================
// QKV GEMM: CTA tile 128x128, BK=32, 256 thr, 8 warps 4(M)x2(N), warp 32x64.
// Two-pass MMA order (hh x16, lh x16). B single fp16.
// 3-stage cp.async, single sync per chunk.
// Stage: AH|AL (128x40 f16 ea = 10240 B) + BH (32x136 f16 = 8704 B) = 29184 B.
// ===========================================================================
#define BM2 128
#define BN2 128
#define BK2 32
#define LDA2 40
#define LDB2 136
#define G2_AH 0
#define G2_AL 10240
#define G2_BH 20480
#define G2_STAGE 29184
#define SM_G2_TOTAL (3 * G2_STAGE)   // 87552
#define NCH2 (D_MODEL / BK2)         // 24

__device__ __forceinline__ void gemm2_issue_loads(
    uint32_t sb, uint32_t stg, int tid, int m0, int n0, int k0,
    const __half* Ah, const __half* Al, const __half* Bh)
{
#pragma unroll
    for (int it = 0; it < 2; it++) {
        const int idx = tid + it * 256;
        // A: 128 rows x 32 k -> 512 uint4
        {
            const int r = idx >> 2, c8 = (idx & 3) * 8;
            const size_t g = (size_t)(m0 + r) * D_MODEL + k0 + c8;
            const uint32_t so = (uint32_t)(r * LDA2 + c8) * 2;
            cp_async16(sb + stg + G2_AH + so, &Ah[g]);
            cp_async16(sb + stg + G2_AL + so, &Al[g]);
        }
        // B: 32 k x 128 n -> 512 uint4
        {
            const int r = idx >> 4, n8 = (idx & 15) * 8;
            const size_t g = (size_t)(k0 + r) * D_MODEL + n0 + n8;
            const uint32_t so = (uint32_t)(r * LDB2 + n8) * 2;
            cp_async16(sb + stg + G2_BH + so, &Bh[g]);
        }
    }
}

__device__ __forceinline__ void gemm2_compute_chunk(
    uint32_t sb, uint32_t stg, int lane, int wm, int wn, float c[2][8][4])
{
    const int a_row = lane & 15;
    const int a_kc  = (lane >> 4) * 8;
    const int b_k   = lane & 15;
    const int b_n   = (lane >> 4) * 8;
#pragma unroll
    for (int ks = 0; ks < BK2 / 16; ks++) {
        uint32_t ah0[4], ah1[4], al0[4], al1[4];
        {
            const uint32_t offH = stg + G2_AH +
                ((wm * 32 + a_row) * LDA2 + ks * 16 + a_kc) * 2;
            ldsm_x4(ah0, sb + offH);
            ldsm_x4(ah1, sb + offH + 16 * LDA2 * 2);
            const uint32_t offL = stg + G2_AL +
                ((wm * 32 + a_row) * LDA2 + ks * 16 + a_kc) * 2;
            ldsm_x4(al0, sb + offL);
            ldsm_x4(al1, sb + offL + 16 * LDA2 * 2);
        }
        uint32_t bh[4][4];
#pragma unroll
        for (int nb = 0; nb < 4; nb++) {
            const uint32_t offB = stg + G2_BH +
                ((ks * 16 + b_k) * LDB2 + wn * 64 + nb * 16 + b_n) * 2;
            ldsm_x4_t(bh[nb], sb + offB);
        }
        // Pass 1: hi*hi — 16 MMAs, distinct accumulators
#pragma unroll
        for (int nb = 0; nb < 4; nb++) {
            mma_f16(c[0][2 * nb],     ah0, bh[nb][0], bh[nb][1]);
            mma_f16(c[1][2 * nb],     ah1, bh[nb][0], bh[nb][1]);
            mma_f16(c[0][2 * nb + 1], ah0, bh[nb][2], bh[nb][3]);
            mma_f16(c[1][2 * nb + 1], ah1, bh[nb][2], bh[nb][3]);
        }
        // Pass 2: lo*hi — 16 MMAs
#pragma unroll
        for (int nb = 0; nb < 4; nb++) {
            mma_f16(c[0][2 * nb],     al0, bh[nb][0], bh[nb][1]);
            mma_f16(c[1][2 * nb],     al1, bh[nb][0], bh[nb][1]);
            mma_f16(c[0][2 * nb + 1], al0, bh[nb][2], bh[nb][3]);
            mma_f16(c[1][2 * nb + 1], al1, bh[nb][2], bh[nb][3]);
        }
    }
}

// blockIdx.z: 0 -> Q (hi/lo, *ALPHA_Q), 1 -> K (single), 2 -> V (single)
__global__ __launch_bounds__(256, 2) void gemm_qkv_kernel(
    const __half* __restrict__ Ah, const __half* __restrict__ Al,
    const __half* __restrict__ whb,
    const float* __restrict__ bq, const float* __restrict__ bk,
    const float* __restrict__ bv,
    __half* __restrict__ qh, __half* __restrict__ ql,
    __half* __restrict__ kh, __half* __restrict__ vh)
{
    extern __shared__ char smg[];
    const uint32_t sb = smem_to_u32(smg);
    const int tid  = threadIdx.x;
    const int lane = tid & 31;
    const int w    = tid >> 5;
    const int wm   = w & 3;
    const int wn   = w >> 2;
    const int m0   = blockIdx.x * BM2;
    const int n0   = blockIdx.y * BN2;
    const int z    = blockIdx.z;

    const __half* Bh = whb + (size_t)z * W_ELEMS;
    const float* bias = (z == 0) ? bq : (z == 1) ? bk : bv;
    const float alpha = (z == 0) ? ALPHA_Q : 1.0f;
    __half* Ch = (z == 0) ? qh : (z == 1) ? kh : vh;

    float c[2][8][4];
#pragma unroll
    for (int mt = 0; mt < 2; mt++)
#pragma unroll
        for (int nt = 0; nt < 8; nt++)
#pragma unroll
            for (int j = 0; j < 4; j++) c[mt][nt][j] = 0.0f;

    // Prologue: prefetch chunks 0 and 1
    gemm2_issue_loads(sb, 0 * G2_STAGE, tid, m0, n0, 0 * BK2, Ah, Al, Bh);
    CP_COMMIT();
    gemm2_issue_loads(sb, 1 * G2_STAGE, tid, m0, n0, 1 * BK2, Ah, Al, Bh);
    CP_COMMIT();

    int s_cur = 0, s_nxt = 2;
    for (int ch = 0; ch < NCH2; ch++) {
        if (ch == NCH2 - 1) { CP_WAIT0(); } else { CP_WAIT1(); }
        __syncthreads();
        if (ch + 2 < NCH2) {
            gemm2_issue_loads(sb, s_nxt * G2_STAGE, tid, m0, n0,
                              (ch + 2) * BK2, Ah, Al, Bh);
            CP_COMMIT();
        }
        gemm2_compute_chunk(sb, s_cur * G2_STAGE, lane, wm, wn, c);
        s_cur = (s_cur == 2) ? 0 : s_cur + 1;
        s_nxt = (s_nxt == 2) ? 0 : s_nxt + 1;
    }

#pragma unroll
    for (int mt = 0; mt < 2; mt++) {
        const int mrow = m0 + wm * 32 + mt * 16 + (lane >> 2);
#pragma unroll
        for (int nt = 0; nt < 8; nt++) {
            const int ncol = n0 + wn * 64 + nt * 8 + (lane & 3) * 2;
            const float b0 = bias[ncol], b1 = bias[ncol + 1];
            const float v00 = alpha * (c[mt][nt][0] + b0);
            const float v01 = alpha * (c[mt][nt][1] + b1);
            const float v10 = alpha * (c[mt][nt][2] + b0);
            const float v11 = alpha * (c[mt][nt][3] + b1);
            const size_t g0 = (size_t)mrow * D_MODEL + ncol;
            const size_t g1 = (size_t)(mrow + 8) * D_MODEL + ncol;
            *reinterpret_cast<uint32_t*>(&Ch[g0]) = cvt_f16x2(v00, v01);
            *reinterpret_cast<uint32_t*>(&Ch[g1]) = cvt_f16x2(v10, v11);
            if (z == 0) {
                *reinterpret_cast<uint32_t*>(&ql[g0]) =
                    cvt_f16x2(v00 - h_rt(v00), v01 - h_rt(v01));
                *reinterpret_cast<uint32_t*>(&ql[g1]) =
                    cvt_f16x2(v10 - h_rt(v10), v11 - h_rt(v11));
            }
        }
    }
}

// ===========================================================================
// O-projection GEMM: BM=64 x BN=128, 256 thr, 8 warps 2(M)x4(N), warp 32x32.
// fp32 output. 3-stage, single sync. Stage: AH|AL (5120 ea) + BH (8704) = 18944.
// ===========================================================================
#define GO_AH 0
#define GO_AL 5120
#define GO_BH 10240
#define GO_STAGE 18944
#define SM_GO_TOTAL (3 * GO_STAGE)   // 56832

__device__ __forceinline__ void gemmo_issue_loads(
    uint32_t sb, uint32_t stg, int tid, int m0, int n0, int k0,
    const __half* Ah, const __half* Al, const __half* Bh)
{
    // A: 64 rows x 32 k -> 256 uint4; 1 per thread
    {
        const int r = tid >> 2, c8 = (tid & 3) * 8;
        const size_t g = (size_t)(m0 + r) * D_MODEL + k0 + c8;
        const uint32_t so = (uint32_t)(r * LDA2 + c8) * 2;
        cp_async16(sb + stg + GO_AH + so, &Ah[g]);
        cp_async16(sb + stg + GO_AL + so, &Al[g]);
    }
    // B: 32 k x 128 n -> 512 uint4; 2 per thread
#pragma unroll
    for (int it = 0; it < 2; it++) {
        const int idx = tid + it * 256;
        const int r = idx >> 4, n8 = (idx & 15) * 8;
        const size_t g = (size_t)(k0 + r) * D_MODEL + n0 + n8;
        const uint32_t so = (uint32_t)(r * LDB2 + n8) * 2;
        cp_async16(sb + stg + GO_BH + so, &Bh[g]);
    }
}

__global__ __launch_bounds__(256, 2) void gemm_o_kernel(
    const __half* __restrict__ Ah, const __half* __restrict__ Al,
    const __half* __restrict__ Bh,
    const float* __restrict__ bias, float* __restrict__ Cf)
{
    extern __shared__ char smg[];
    const uint32_t sb = smem_to_u32(smg);
    const int tid  = threadIdx.x;
    const int lane = tid & 31;
    const int w    = tid >> 5;
    const int wm   = w & 1;
    const int wn   = w >> 1;
    const int m0   = blockIdx.x * 64;
    const int n0   = blockIdx.y * 128;

    const int a_row = lane & 15;
    const int a_kc  = (lane >> 4) * 8;
    const int b_k   = lane & 15;
    const int b_n   = (lane >> 4) * 8;

    float c[2][4][4];
#pragma unroll
    for (int mt = 0; mt < 2; mt++)
#pragma unroll
        for (int nt = 0; nt < 4; nt++)
#pragma unroll
            for (int j = 0; j < 4; j++) c[mt][nt][j] = 0.0f;

    gemmo_issue_loads(sb, 0 * GO_STAGE, tid, m0, n0, 0 * BK2, Ah, Al, Bh);
    CP_COMMIT();
    gemmo_issue_loads(sb, 1 * GO_STAGE, tid, m0, n0, 1 * BK2, Ah, Al, Bh);
    CP_COMMIT();

    int s_cur = 0, s_nxt = 2;
    for (int ch = 0; ch < NCH2; ch++) {
        if (ch == NCH2 - 1) { CP_WAIT0(); } else { CP_WAIT1(); }
        __syncthreads();
        if (ch + 2 < NCH2) {
            gemmo_issue_loads(sb, s_nxt * GO_STAGE, tid, m0, n0,
                              (ch + 2) * BK2, Ah, Al, Bh);
            CP_COMMIT();
        }
        const uint32_t cur = s_cur * GO_STAGE;

#pragma unroll
        for (int ks = 0; ks < BK2 / 16; ks++) {
            uint32_t ah0[4], ah1[4], al0[4], al1[4];
            {
                const uint32_t offH = cur + GO_AH +
                    ((wm * 32 + a_row) * LDA2 + ks * 16 + a_kc) * 2;
                ldsm_x4(ah0, sb + offH);
                ldsm_x4(ah1, sb + offH + 16 * LDA2 * 2);
                const uint32_t offL = cur + GO_AL +
                    ((wm * 32 + a_row) * LDA2 + ks * 16 + a_kc) * 2;
                ldsm_x4(al0, sb + offL);
                ldsm_x4(al1, sb + offL + 16 * LDA2 * 2);
            }
            uint32_t bh[2][4];
#pragma unroll
            for (int nb = 0; nb < 2; nb++) {
                const uint32_t offB = cur + GO_BH +
                    ((ks * 16 + b_k) * LDB2 + wn * 32 + nb * 16 + b_n) * 2;
                ldsm_x4_t(bh[nb], sb + offB);
            }
#pragma unroll
            for (int nb = 0; nb < 2; nb++) {
                mma_f16(c[0][2 * nb],     ah0, bh[nb][0], bh[nb][1]);
                mma_f16(c[1][2 * nb],     ah1, bh[nb][0], bh[nb][1]);
                mma_f16(c[0][2 * nb + 1], ah0, bh[nb][2], bh[nb][3]);
                mma_f16(c[1][2 * nb + 1], ah1, bh[nb][2], bh[nb][3]);
            }
#pragma unroll
            for (int nb = 0; nb < 2; nb++) {
                mma_f16(c[0][2 * nb],     al0, bh[nb][0], bh[nb][1]);
                mma_f16(c[1][2 * nb],     al1, bh[nb][0], bh[nb][1]);
                mma_f16(c[0][2 * nb + 1], al0, bh[nb][2], bh[nb][3]);
                mma_f16(c[1][2 * nb + 1], al1, bh[nb][2], bh[nb][3]);
            }
        }
        s_cur = (s_cur == 2) ? 0 : s_cur + 1;
        s_nxt = (s_nxt == 2) ? 0 : s_nxt + 1;
    }

#pragma unroll
    for (int mt = 0; mt < 2; mt++) {
        const int mrow = m0 + wm * 32 + mt * 16 + (lane >> 2);
#pragma unroll
        for (int nt = 0; nt < 4; nt++) {
            const int ncol = n0 + wn * 32 + nt * 8 + (lane & 3) * 2;
            const float b0 = bias[ncol], b1 = bias[ncol + 1];
            float2 o0 = make_float2(c[mt][nt][0] + b0, c[mt][nt][1] + b1);
            float2 o1 = make_float2(c[mt][nt][2] + b0, c[mt][nt][3] + b1);
            *reinterpret_cast<float2*>(&Cf[(size_t)mrow * D_MODEL + ncol]) = o0;
            *reinterpret_cast<float2*>(&Cf[(size_t)(mrow + 8) * D_MODEL + ncol]) = o1;
        }
    }
}

// ===========================================================================
// fp16 flash attention: BQ=128, 256 thr. Q hi/lo; K,V single fp16.
// S = QhK + QlK; ctx = PhV + PlV. exp2-domain softmax.
// 3-stage cp.async on K/V tiles, single sync per tile.
// smem: Q (hi+lo) 36864 + 3 stages x (KH|VH = 18432) = 92160 B.
// ===========================================================================
#define AT_LD 72
#define A_QH 0
#define A_QL 18432
#define A_QSZ 36864
#define A_KH 0
#define A_VH 9216
#define A_STAGE 18432
#define A_SM_TOTAL (A_QSZ + 3 * A_STAGE)   // 92160

__device__ __forceinline__ void attn_issue_loads(
    uint32_t sb, uint32_t stg, int tid, size_t rbase, int kt, int hcol,
    const __half* Kh, const __half* Vh)
{
    const int r  = tid >> 3;
    const int c8 = (tid & 7) * 8;
#pragma unroll
    for (int it = 0; it < 2; it++) {
        const int rr = r + it * 32;
        const size_t g = (rbase + kt + rr) * D_MODEL + hcol + c8;
        const uint32_t so = (uint32_t)(rr * AT_LD + c8) * 2;
        cp_async16(sb + stg + A_KH + so, &Kh[g]);
        cp_async16(sb + stg + A_VH + so, &Vh[g]);
    }
}

__global__ __launch_bounds__(256, 2) void attn_hmma_kernel(
    const __half* __restrict__ Qh, const __half* __restrict__ Ql,
    const __half* __restrict__ Kh, const __half* __restrict__ Vh,
    __half* __restrict__ Ch, __half* __restrict__ Cl)
{
    extern __shared__ char sma[];
    const uint32_t sb = smem_to_u32(sma);
    const int tid  = threadIdx.x;
    const int lane = tid & 31;
    const int w    = tid >> 5;
    const int q0   = blockIdx.x * 128;
    const int h    = blockIdx.y;
    const int b    = blockIdx.z;
    const int hcol = h * HD;
    const size_t rbase = (size_t)b * S_LEN;

    const int l_row = lane & 15;
    const int l_c8  = (lane >> 4) * 8;

    // Prologue: prefetch K/V tiles 0 and 1
    attn_issue_loads(sb, A_QSZ + 0 * A_STAGE, tid, rbase, 0 * 64, hcol, Kh, Vh);
    CP_COMMIT();
    attn_issue_loads(sb, A_QSZ + 1 * A_STAGE, tid, rbase, 1 * 64, hcol, Kh, Vh);
    CP_COMMIT();

    // Q tile (regular stores; visible after first in-loop syncthreads)
    {
        const int r = tid >> 3;
        const int c8 = (tid & 7) * 8;
#pragma unroll
        for (int it = 0; it < 4; it++) {
            const int rr = r + it * 32;
            const size_t g = (rbase + q0 + rr) * D_MODEL + hcol + c8;
            *reinterpret_cast<uint4*>(sma + A_QH + (rr * AT_LD + c8) * 2) =
                *reinterpret_cast<const uint4*>(&Qh[g]);
            *reinterpret_cast<uint4*>(sma + A_QL + (rr * AT_LD + c8) * 2) =
                *reinterpret_cast<const uint4*>(&Ql[g]);
        }
    }

    float ctx[8][4];
#pragma unroll
    for (int nt = 0; nt < 8; nt++)
#pragma unroll
        for (int j = 0; j < 4; j++) ctx[nt][j] = 0.0f;
    float m0r = -INFINITY, m1r = -INFINITY, l0r = 0.0f, l1r = 0.0f;

    const int NT = S_LEN / 64;
    int s_cur = 0, s_nxt = 2;
    for (int ti = 0; ti < NT; ti++) {
        if (ti == NT - 1) { CP_WAIT0(); } else { CP_WAIT1(); }
        __syncthreads();
        if (ti + 2 < NT) {
            attn_issue_loads(sb, A_QSZ + s_nxt * A_STAGE,
                             tid, rbase, (ti + 2) * 64, hcol, Kh, Vh);
            CP_COMMIT();
        }
        const uint32_t cur = A_QSZ + s_cur * A_STAGE;

        // ---- S = Q K^T, 2-term split
        float S[8][4];
#pragma unroll
        for (int nt = 0; nt < 8; nt++)
#pragma unroll
            for (int j = 0; j < 4; j++) S[nt][j] = 0.0f;

#pragma unroll
        for (int ks = 0; ks < 4; ks++) {
            uint32_t qh[4], ql[4];
            const uint32_t qoff = ((w * 16 + l_row) * AT_LD + ks * 16 + l_c8) * 2;
            ldsm_x4(qh, sb + A_QH + qoff);
            ldsm_x4(ql, sb + A_QL + qoff);
#pragma unroll
            for (int g = 0; g < 4; g++) {
                uint32_t kh[4];
                const uint32_t koff = cur + A_KH +
                    ((g * 16 + l_row) * AT_LD + ks * 16 + l_c8) * 2;
                ldsm_x4(kh, sb + koff);
                mma_f16(S[2 * g],     qh, kh[0], kh[2]);
                mma_f16(S[2 * g + 1], qh, kh[1], kh[3]);
                mma_f16(S[2 * g],     ql, kh[0], kh[2]);
                mma_f16(S[2 * g + 1], ql, kh[1], kh[3]);
            }
        }

        // ---- online softmax (exp2 domain)
        float mx0 = -INFINITY, mx1 = -INFINITY;
#pragma unroll
        for (int nt = 0; nt < 8; nt++) {
            mx0 = fmaxf(mx0, fmaxf(S[nt][0], S[nt][1]));
            mx1 = fmaxf(mx1, fmaxf(S[nt][2], S[nt][3]));
        }
        mx0 = fmaxf(mx0, __shfl_xor_sync(0xffffffffu, mx0, 1));
        mx0 = fmaxf(mx0, __shfl_xor_sync(0xffffffffu, mx0, 2));
        mx1 = fmaxf(mx1, __shfl_xor_sync(0xffffffffu, mx1, 1));
        mx1 = fmaxf(mx1, __shfl_xor_sync(0xffffffffu, mx1, 2));
        const float mn0 = fmaxf(m0r, mx0);
        const float mn1 = fmaxf(m1r, mx1);
        const float cr0 = exp2f(m0r - mn0);
        const float cr1 = exp2f(m1r - mn1);
        float s0 = 0.0f, s1 = 0.0f;
#pragma unroll
        for (int nt = 0; nt < 8; nt++) {
            S[nt][0] = exp2f(S[nt][0] - mn0);
            S[nt][1] = exp2f(S[nt][1] - mn0);
            S[nt][2] = exp2f(S[nt][2] - mn1);
            S[nt][3] = exp2f(S[nt][3] - mn1);
            s0 += S[nt][0] + S[nt][1];
            s1 += S[nt][2] + S[nt][3];
            ctx[nt][0] *= cr0; ctx[nt][1] *= cr0;
            ctx[nt][2] *= cr1; ctx[nt][3] *= cr1;
        }
        s0 += __shfl_xor_sync(0xffffffffu, s0, 1);
        s0 += __shfl_xor_sync(0xffffffffu, s0, 2);
        s1 += __shfl_xor_sync(0xffffffffu, s1, 1);
        s1 += __shfl_xor_sync(0xffffffffu, s1, 2);
        l0r = l0r * cr0 + s0;
        l1r = l1r * cr1 + s1;
        m0r = mn0;
        m1r = mn1;

        // ---- pack P into a-frags (hi + lo, fp16)
        uint32_t ph[4][4], pl[4][4];
#pragma unroll
        for (int j = 0; j < 4; j++) {
            const float p0 = S[2 * j][0],     p1 = S[2 * j][1];
            const float p2 = S[2 * j][2],     p3 = S[2 * j][3];
            const float p4 = S[2 * j + 1][0], p5 = S[2 * j + 1][1];
            const float p6 = S[2 * j + 1][2], p7 = S[2 * j + 1][3];
            ph[j][0] = cvt_f16x2(p0, p1);
            ph[j][1] = cvt_f16x2(p2, p3);
            ph[j][2] = cvt_f16x2(p4, p5);
            ph[j][3] = cvt_f16x2(p6, p7);
            pl[j][0] = cvt_f16x2(p0 - h_rt(p0), p1 - h_rt(p1));
            pl[j][1] = cvt_f16x2(p2 - h_rt(p2), p3 - h_rt(p3));
            pl[j][2] = cvt_f16x2(p4 - h_rt(p4), p5 - h_rt(p5));
            pl[j][3] = cvt_f16x2(p6 - h_rt(p6), p7 - h_rt(p7));
        }

        // ---- ctx += P V, 2-term
#pragma unroll
        for (int kc = 0; kc < 4; kc++) {
#pragma unroll
            for (int dg = 0; dg < 4; dg++) {
                uint32_t vh[4];
                const uint32_t voff = cur + A_VH +
                    ((kc * 16 + l_row) * AT_LD + dg * 16 + l_c8) * 2;
                ldsm_x4_t(vh, sb + voff);
                mma_f16(ctx[2 * dg],     ph[kc], vh[0], vh[1]);
                mma_f16(ctx[2 * dg + 1], ph[kc], vh[2], vh[3]);
                mma_f16(ctx[2 * dg],     pl[kc], vh[0], vh[1]);
                mma_f16(ctx[2 * dg + 1], pl[kc], vh[2], vh[3]);
            }
        }
        s_cur = (s_cur == 2) ? 0 : s_cur + 1;
        s_nxt = (s_nxt == 2) ? 0 : s_nxt + 1;
    }

    // ---- epilogue: normalize, split, store ctx hi/lo (fp16)
    const float inv0 = 1.0f / l0r;
    const float inv1 = 1.0f / l1r;
    const int row0 = q0 + w * 16 + (lane >> 2);
#pragma unroll
    for (int nt = 0; nt < 8; nt++) {
        const int col = hcol + nt * 8 + (lane & 3) * 2;
        const float v00 = ctx[nt][0] * inv0, v01 = ctx[nt][1] * inv0;
        const float v10 = ctx[nt][2] * inv1, v11 = ctx[nt][3] * inv1;
        const size_t g0 = (rbase + row0) * D_MODEL + col;
        const size_t g1 = (rbase + row0 + 8) * D_MODEL + col;
        *reinterpret_cast<uint32_t*>(&Ch[g0]) = cvt_f16x2(v00, v01);
        *reinterpret_cast<uint32_t*>(&Ch[g1]) = cvt_f16x2(v10, v11);
        *reinterpret_cast<uint32_t*>(&Cl[g0]) =
            cvt_f16x2(v00 - h_rt(v00), v01 - h_rt(v01));
        *reinterpret_cast<uint32_t*>(&Cl[g1]) =
            cvt_f16x2(v10 - h_rt(v10), v11 - h_rt(v11));
    }
}

// ---------------------------------------------------------------------------
// Launch
// ---------------------------------------------------------------------------
extern "C" void kernel_launch(void* const* d_in, const int* in_sizes, int n_in,
                              void* d_out, int out_size)
{
    const float* x  = (const float*)d_in[0];
    const float* Wq = (const float*)d_in[1];
    const float* bq = (const float*)d_in[2];
    const float* Wk = (const float*)d_in[3];
    const float* bk = (const float*)d_in[4];
    const float* Wv = (const float*)d_in[5];
    const float* bv = (const float*)d_in[6];
    const float* Wo = (const float*)d_in[7];
    const float* bo = (const float*)d_in[8];
    float* out = (float*)d_out;

    __half *xh, *xl, *wh, *qh, *ql, *kh, *vh, *ch, *cl;
    cudaGetSymbolAddress((void**)&xh, g_xh);
    cudaGetSymbolAddress((void**)&xl, g_xl);
    cudaGetSymbolAddress((void**)&wh, g_wh);
    cudaGetSymbolAddress((void**)&qh, g_qh);
    cudaGetSymbolAddress((void**)&ql, g_ql);
    cudaGetSymbolAddress((void**)&kh, g_kh);
    cudaGetSymbolAddress((void**)&vh, g_vh);
    cudaGetSymbolAddress((void**)&ch, g_ch);
    cudaGetSymbolAddress((void**)&cl, g_cl);

    cudaFuncSetAttribute(gemm_qkv_kernel,
                         cudaFuncAttributeMaxDynamicSharedMemorySize,
                         SM_G2_TOTAL);
    cudaFuncSetAttribute(gemm_o_kernel,
                         cudaFuncAttributeMaxDynamicSharedMemorySize,
                         SM_GO_TOTAL);
    cudaFuncSetAttribute(attn_hmma_kernel,
                         cudaFuncAttributeMaxDynamicSharedMemorySize,
                         A_SM_TOTAL);

    // Split: each thread does 4 strided float4s. Largest quarter = 196608
    // float4s -> 768 blocks; weight tensors bound-check internally.
    dim3 split_grid((M_ROWS * D_MODEL / 16 + 255) / 256, 5);
    split_all_kernel<<<split_grid, 256>>>(x, Wq, Wk, Wv, Wo, xh, xl, wh);

    dim3 qkv_grid(M_ROWS / BM2, D_MODEL / BN2, 3);   // 32 x 6 x 3 = 576
    gemm_qkv_kernel<<<qkv_grid, 256, SM_G2_TOTAL>>>(
        xh, xl, wh, bq, bk, bv, qh, ql, kh, vh);

    dim3 attn_grid(S_LEN / 128, H_NUM, B_SZ);        // 16 x 12 x 2 = 384
    attn_hmma_kernel<<<attn_grid, 256, A_SM_TOTAL>>>(
        qh, ql, kh, vh, ch, cl);

    dim3 o_grid(M_ROWS / 64, D_MODEL / 128);         // 64 x 6 = 384
    gemm_o_kernel<<<o_grid, 256, SM_GO_TOTAL>>>(
        ch, cl, wh + 3 * W_ELEMS, bo, out);
}

// round 15
// speedup vs baseline: 1.5529x; 1.0137x over previous
#include <cuda_runtime.h>
#include <cuda_fp16.h>
#include <cstdint>
#include <math.h>

// Problem constants
#define S_LEN   2048
#define D_MODEL 768
#define H_NUM   12
#define HD      64
#define B_SZ    2
#define M_ROWS  (B_SZ * S_LEN)   // 4096
#define W_ELEMS (D_MODEL * D_MODEL)

// Q pre-scale: 1/sqrt(64) * log2(e)  (softmax done in exp2 domain)
#define ALPHA_Q (0.125f * 1.44269504088896f)

// Scratch (allocation-free rule: __device__ globals). fp16.
// A-side tensors (x, q, ctx) keep hi/lo; B-side (W, k, v) single fp16.
__device__ __half g_xh[M_ROWS * D_MODEL];
__device__ __half g_xl[M_ROWS * D_MODEL];
__device__ __half g_wh[4 * W_ELEMS];
__device__ __half g_qh[M_ROWS * D_MODEL];
__device__ __half g_ql[M_ROWS * D_MODEL];
__device__ __half g_kh[M_ROWS * D_MODEL];
__device__ __half g_vh[M_ROWS * D_MODEL];
__device__ __half g_ch[M_ROWS * D_MODEL];
__device__ __half g_cl[M_ROWS * D_MODEL];

// ===========================================================================
// Warp-MMA + async-copy helpers
// ===========================================================================
__device__ __forceinline__ uint32_t smem_to_u32(const void* p) {
    uint32_t a;
    asm("{ .reg .u64 t; cvta.to.shared.u64 t, %1; cvt.u32.u64 %0, t; }"
        : "=r"(a) : "l"(p));
    return a;
}
__device__ __forceinline__ void ldsm_x4(uint32_t* r, uint32_t addr) {
    asm volatile(
        "ldmatrix.sync.aligned.m8n8.x4.shared.b16 {%0,%1,%2,%3}, [%4];"
        : "=r"(r[0]), "=r"(r[1]), "=r"(r[2]), "=r"(r[3]) : "r"(addr));
}
__device__ __forceinline__ void ldsm_x4_t(uint32_t* r, uint32_t addr) {
    asm volatile(
        "ldmatrix.sync.aligned.m8n8.x4.trans.shared.b16 {%0,%1,%2,%3}, [%4];"
        : "=r"(r[0]), "=r"(r[1]), "=r"(r[2]), "=r"(r[3]) : "r"(addr));
}
__device__ __forceinline__ void mma_f16(float* c, const uint32_t* a,
                                        uint32_t b0, uint32_t b1) {
    asm volatile(
        "mma.sync.aligned.m16n8k16.row.col.f32.f16.f16.f32 "
        "{%0,%1,%2,%3}, {%4,%5,%6,%7}, {%8,%9}, {%0,%1,%2,%3};"
        : "+f"(c[0]), "+f"(c[1]), "+f"(c[2]), "+f"(c[3])
        : "r"(a[0]), "r"(a[1]), "r"(a[2]), "r"(a[3]), "r"(b0), "r"(b1));
}
// pack two floats into f16x2; first arg = lower-address element
__device__ __forceinline__ uint32_t cvt_f16x2(float lo, float hi) {
    uint32_t r;
    asm("cvt.rn.f16x2.f32 %0, %1, %2;" : "=r"(r) : "f"(hi), "f"(lo));
    return r;
}
__device__ __forceinline__ float h_rt(float x) {
    return __half2float(__float2half_rn(x));
}
__device__ __forceinline__ void cp_async16(uint32_t dst, const void* src) {
    asm volatile("cp.async.cg.shared.global [%0], [%1], 16;"
                 :: "r"(dst), "l"(src) : "memory");
}
#define CP_COMMIT() asm volatile("cp.async.commit_group;" ::: "memory")
#define CP_WAIT1()  asm volatile("cp.async.wait_group 1;" ::: "memory")
#define CP_WAIT0()  asm volatile("cp.async.wait_group 0;" ::: "memory")

// ===========================================================================
// Fused split: x -> (fp16 hi, fp16 lo); weights -> fp16 hi only.
// Each thread handles 4 strided float4s (MLP=4; splits were latency-bound).
// ===========================================================================
__global__ __launch_bounds__(256) void split_all_kernel(
    const float* __restrict__ x,
    const float* __restrict__ Wq, const float* __restrict__ Wk,
    const float* __restrict__ Wv, const float* __restrict__ Wo,
    __half* __restrict__ xh, __half* __restrict__ xl,
    __half* __restrict__ wh)
{
    const int t = blockIdx.y;
    const float* src;
    __half *hi, *lo = nullptr;
    int n4;
    if (t == 0) { src = x;  hi = xh; lo = xl; n4 = M_ROWS * D_MODEL / 4; }
    else {
        const float* ws[4] = {Wq, Wk, Wv, Wo};
        src = ws[t - 1];
        hi = wh + (size_t)(t - 1) * W_ELEMS;
        n4 = W_ELEMS / 4;
    }
    const int q = n4 >> 2;   // quarter stride
    const int i0 = blockIdx.x * blockDim.x + threadIdx.x;
    if (i0 >= q) return;
#pragma unroll
    for (int it = 0; it < 4; it++) {
        const int i = i0 + it * q;
        float4 v = reinterpret_cast<const float4*>(src)[i];
        uint32_t* hp = reinterpret_cast<uint32_t*>(hi) + 2 * i;
        hp[0] = cvt_f16x2(v.x, v.y);
        hp[1] = cvt_f16x2(v.z, v.w);
        if (lo) {
            uint32_t* lp = reinterpret_cast<uint32_t*>(lo) + 2 * i;
            lp[0] = cvt_f16x2(v.x - h_rt(v.x), v.y - h_rt(v.y));
            lp[1] = cvt_f16x2(v.z - h_rt(v.z), v.w - h_rt(v.w));
        }
    }
}

// ===========================================================================
// QKV GEMM: CTA tile 128x128, BK=32, 256 thr, 8 warps 4(M)x2(N), warp 32x64.
// Two-pass MMA order (hh x16, lh x16). B single fp16.
// 3-stage cp.async, single sync per chunk.
// Stage: AH|AL (128x40 f16 ea = 10240 B) + BH (32x136 f16 = 8704 B) = 29184 B.
// ===========================================================================
#define BM2 128
#define BN2 128
#define BK2 32
#define LDA2 40
#define LDB2 136
#define G2_AH 0
#define G2_AL 10240
#define G2_BH 20480
#define G2_STAGE 29184
#define SM_G2_TOTAL (3 * G2_STAGE)   // 87552
#define NCH2 (D_MODEL / BK2)         // 24

__device__ __forceinline__ void gemm2_issue_loads(
    uint32_t sb, uint32_t stg, int tid, int m0, int n0, int k0,
    const __half* Ah, const __half* Al, const __half* Bh)
{
#pragma unroll
    for (int it = 0; it < 2; it++) {
        const int idx = tid + it * 256;
        // A: 128 rows x 32 k -> 512 uint4
        {
            const int r = idx >> 2, c8 = (idx & 3) * 8;
            const size_t g = (size_t)(m0 + r) * D_MODEL + k0 + c8;
            const uint32_t so = (uint32_t)(r * LDA2 + c8) * 2;
            cp_async16(sb + stg + G2_AH + so, &Ah[g]);
            cp_async16(sb + stg + G2_AL + so, &Al[g]);
        }
        // B: 32 k x 128 n -> 512 uint4
        {
            const int r = idx >> 4, n8 = (idx & 15) * 8;
            const size_t g = (size_t)(k0 + r) * D_MODEL + n0 + n8;
            const uint32_t so = (uint32_t)(r * LDB2 + n8) * 2;
            cp_async16(sb + stg + G2_BH + so, &Bh[g]);
        }
    }
}

__device__ __forceinline__ void gemm2_compute_chunk(
    uint32_t sb, uint32_t stg, int lane, int wm, int wn, float c[2][8][4])
{
    const int a_row = lane & 15;
    const int a_kc  = (lane >> 4) * 8;
    const int b_k   = lane & 15;
    const int b_n   = (lane >> 4) * 8;
#pragma unroll
    for (int ks = 0; ks < BK2 / 16; ks++) {
        uint32_t ah0[4], ah1[4], al0[4], al1[4];
        {
            const uint32_t offH = stg + G2_AH +
                ((wm * 32 + a_row) * LDA2 + ks * 16 + a_kc) * 2;
            ldsm_x4(ah0, sb + offH);
            ldsm_x4(ah1, sb + offH + 16 * LDA2 * 2);
            const uint32_t offL = stg + G2_AL +
                ((wm * 32 + a_row) * LDA2 + ks * 16 + a_kc) * 2;
            ldsm_x4(al0, sb + offL);
            ldsm_x4(al1, sb + offL + 16 * LDA2 * 2);
        }
        uint32_t bh[4][4];
#pragma unroll
        for (int nb = 0; nb < 4; nb++) {
            const uint32_t offB = stg + G2_BH +
                ((ks * 16 + b_k) * LDB2 + wn * 64 + nb * 16 + b_n) * 2;
            ldsm_x4_t(bh[nb], sb + offB);
        }
        // Pass 1: hi*hi — 16 MMAs, distinct accumulators
#pragma unroll
        for (int nb = 0; nb < 4; nb++) {
            mma_f16(c[0][2 * nb],     ah0, bh[nb][0], bh[nb][1]);
            mma_f16(c[1][2 * nb],     ah1, bh[nb][0], bh[nb][1]);
            mma_f16(c[0][2 * nb + 1], ah0, bh[nb][2], bh[nb][3]);
            mma_f16(c[1][2 * nb + 1], ah1, bh[nb][2], bh[nb][3]);
        }
        // Pass 2: lo*hi — 16 MMAs
#pragma unroll
        for (int nb = 0; nb < 4; nb++) {
            mma_f16(c[0][2 * nb],     al0, bh[nb][0], bh[nb][1]);
            mma_f16(c[1][2 * nb],     al1, bh[nb][0], bh[nb][1]);
            mma_f16(c[0][2 * nb + 1], al0, bh[nb][2], bh[nb][3]);
            mma_f16(c[1][2 * nb + 1], al1, bh[nb][2], bh[nb][3]);
        }
    }
}

// blockIdx.z: 0 -> Q (hi/lo, *ALPHA_Q), 1 -> K (single), 2 -> V (single)
__global__ __launch_bounds__(256, 2) void gemm_qkv_kernel(
    const __half* __restrict__ Ah, const __half* __restrict__ Al,
    const __half* __restrict__ whb,
    const float* __restrict__ bq, const float* __restrict__ bk,
    const float* __restrict__ bv,
    __half* __restrict__ qh, __half* __restrict__ ql,
    __half* __restrict__ kh, __half* __restrict__ vh)
{
    extern __shared__ char smg[];
    const uint32_t sb = smem_to_u32(smg);
    const int tid  = threadIdx.x;
    const int lane = tid & 31;
    const int w    = tid >> 5;
    const int wm   = w & 3;
    const int wn   = w >> 2;
    const int m0   = blockIdx.x * BM2;
    const int n0   = blockIdx.y * BN2;
    const int z    = blockIdx.z;

    const __half* Bh = whb + (size_t)z * W_ELEMS;
    const float* bias = (z == 0) ? bq : (z == 1) ? bk : bv;
    const float alpha = (z == 0) ? ALPHA_Q : 1.0f;
    __half* Ch = (z == 0) ? qh : (z == 1) ? kh : vh;

    float c[2][8][4];
#pragma unroll
    for (int mt = 0; mt < 2; mt++)
#pragma unroll
        for (int nt = 0; nt < 8; nt++)
#pragma unroll
            for (int j = 0; j < 4; j++) c[mt][nt][j] = 0.0f;

    // Prologue: prefetch chunks 0 and 1
    gemm2_issue_loads(sb, 0 * G2_STAGE, tid, m0, n0, 0 * BK2, Ah, Al, Bh);
    CP_COMMIT();
    gemm2_issue_loads(sb, 1 * G2_STAGE, tid, m0, n0, 1 * BK2, Ah, Al, Bh);
    CP_COMMIT();

    int s_cur = 0, s_nxt = 2;
    for (int ch = 0; ch < NCH2; ch++) {
        if (ch == NCH2 - 1) { CP_WAIT0(); } else { CP_WAIT1(); }
        __syncthreads();
        if (ch + 2 < NCH2) {
            gemm2_issue_loads(sb, s_nxt * G2_STAGE, tid, m0, n0,
                              (ch + 2) * BK2, Ah, Al, Bh);
            CP_COMMIT();
        }
        gemm2_compute_chunk(sb, s_cur * G2_STAGE, lane, wm, wn, c);
        s_cur = (s_cur == 2) ? 0 : s_cur + 1;
        s_nxt = (s_nxt == 2) ? 0 : s_nxt + 1;
    }

#pragma unroll
    for (int mt = 0; mt < 2; mt++) {
        const int mrow = m0 + wm * 32 + mt * 16 + (lane >> 2);
#pragma unroll
        for (int nt = 0; nt < 8; nt++) {
            const int ncol = n0 + wn * 64 + nt * 8 + (lane & 3) * 2;
            const float b0 = bias[ncol], b1 = bias[ncol + 1];
            const float v00 = alpha * (c[mt][nt][0] + b0);
            const float v01 = alpha * (c[mt][nt][1] + b1);
            const float v10 = alpha * (c[mt][nt][2] + b0);
            const float v11 = alpha * (c[mt][nt][3] + b1);
            const size_t g0 = (size_t)mrow * D_MODEL + ncol;
            const size_t g1 = (size_t)(mrow + 8) * D_MODEL + ncol;
            *reinterpret_cast<uint32_t*>(&Ch[g0]) = cvt_f16x2(v00, v01);
            *reinterpret_cast<uint32_t*>(&Ch[g1]) = cvt_f16x2(v10, v11);
            if (z == 0) {
                *reinterpret_cast<uint32_t*>(&ql[g0]) =
                    cvt_f16x2(v00 - h_rt(v00), v01 - h_rt(v01));
                *reinterpret_cast<uint32_t*>(&ql[g1]) =
                    cvt_f16x2(v10 - h_rt(v10), v11 - h_rt(v11));
            }
        }
    }
}

// ===========================================================================
// O-projection GEMM: BM=64 x BN=128, 256 thr, 8 warps 2(M)x4(N), warp 32x32.
// fp32 output. 4-stage ring, TWO chunks per barrier (12 barriers total).
// Stage: AH|AL (5120 ea) + BH (8704) = 18944; 4 stages = 75776 B.
// ===========================================================================
#define GO_AH 0
#define GO_AL 5120
#define GO_BH 10240
#define GO_STAGE 18944
#define SM_GO_TOTAL (4 * GO_STAGE)   // 75776

__device__ __forceinline__ void gemmo_issue_loads(
    uint32_t sb, uint32_t stg, int tid, int m0, int n0, int k0,
    const __half* Ah, const __half* Al, const __half* Bh)
{
    // A: 64 rows x 32 k -> 256 uint4; 1 per thread
    {
        const int r = tid >> 2, c8 = (tid & 3) * 8;
        const size_t g = (size_t)(m0 + r) * D_MODEL + k0 + c8;
        const uint32_t so = (uint32_t)(r * LDA2 + c8) * 2;
        cp_async16(sb + stg + GO_AH + so, &Ah[g]);
        cp_async16(sb + stg + GO_AL + so, &Al[g]);
    }
    // B: 32 k x 128 n -> 512 uint4; 2 per thread
#pragma unroll
    for (int it = 0; it < 2; it++) {
        const int idx = tid + it * 256;
        const int r = idx >> 4, n8 = (idx & 15) * 8;
        const size_t g = (size_t)(k0 + r) * D_MODEL + n0 + n8;
        const uint32_t so = (uint32_t)(r * LDB2 + n8) * 2;
        cp_async16(sb + stg + GO_BH + so, &Bh[g]);
    }
}

__device__ __forceinline__ void gemmo_compute_chunk(
    uint32_t sb, uint32_t cur, int lane, int wm, int wn, float c[2][4][4])
{
    const int a_row = lane & 15;
    const int a_kc  = (lane >> 4) * 8;
    const int b_k   = lane & 15;
    const int b_n   = (lane >> 4) * 8;
#pragma unroll
    for (int ks = 0; ks < BK2 / 16; ks++) {
        uint32_t ah0[4], ah1[4], al0[4], al1[4];
        {
            const uint32_t offH = cur + GO_AH +
                ((wm * 32 + a_row) * LDA2 + ks * 16 + a_kc) * 2;
            ldsm_x4(ah0, sb + offH);
            ldsm_x4(ah1, sb + offH + 16 * LDA2 * 2);
            const uint32_t offL = cur + GO_AL +
                ((wm * 32 + a_row) * LDA2 + ks * 16 + a_kc) * 2;
            ldsm_x4(al0, sb + offL);
            ldsm_x4(al1, sb + offL + 16 * LDA2 * 2);
        }
        uint32_t bh[2][4];
#pragma unroll
        for (int nb = 0; nb < 2; nb++) {
            const uint32_t offB = cur + GO_BH +
                ((ks * 16 + b_k) * LDB2 + wn * 32 + nb * 16 + b_n) * 2;
            ldsm_x4_t(bh[nb], sb + offB);
        }
#pragma unroll
        for (int nb = 0; nb < 2; nb++) {
            mma_f16(c[0][2 * nb],     ah0, bh[nb][0], bh[nb][1]);
            mma_f16(c[1][2 * nb],     ah1, bh[nb][0], bh[nb][1]);
            mma_f16(c[0][2 * nb + 1], ah0, bh[nb][2], bh[nb][3]);
            mma_f16(c[1][2 * nb + 1], ah1, bh[nb][2], bh[nb][3]);
        }
#pragma unroll
        for (int nb = 0; nb < 2; nb++) {
            mma_f16(c[0][2 * nb],     al0, bh[nb][0], bh[nb][1]);
            mma_f16(c[1][2 * nb],     al1, bh[nb][0], bh[nb][1]);
            mma_f16(c[0][2 * nb + 1], al0, bh[nb][2], bh[nb][3]);
            mma_f16(c[1][2 * nb + 1], al1, bh[nb][2], bh[nb][3]);
        }
    }
}

__global__ __launch_bounds__(256, 2) void gemm_o_kernel(
    const __half* __restrict__ Ah, const __half* __restrict__ Al,
    const __half* __restrict__ Bh,
    const float* __restrict__ bias, float* __restrict__ Cf)
{
    extern __shared__ char smg[];
    const uint32_t sb = smem_to_u32(smg);
    const int tid  = threadIdx.x;
    const int lane = tid & 31;
    const int w    = tid >> 5;
    const int wm   = w & 1;
    const int wn   = w >> 1;
    const int m0   = blockIdx.x * 64;
    const int n0   = blockIdx.y * 128;

    float c[2][4][4];
#pragma unroll
    for (int mt = 0; mt < 2; mt++)
#pragma unroll
        for (int nt = 0; nt < 4; nt++)
#pragma unroll
            for (int j = 0; j < 4; j++) c[mt][nt][j] = 0.0f;

    // Prologue: pair 0 (chunks 0,1)
    gemmo_issue_loads(sb, 0 * GO_STAGE, tid, m0, n0, 0 * BK2, Ah, Al, Bh);
    CP_COMMIT();
    gemmo_issue_loads(sb, 1 * GO_STAGE, tid, m0, n0, 1 * BK2, Ah, Al, Bh);
    CP_COMMIT();

    const int NP = NCH2 / 2;   // 12 pairs
    for (int p = 0; p < NP; p++) {
        CP_WAIT0();
        __syncthreads();
        if (p + 1 < NP) {
            const int c0 = 2 * p + 2, c1 = 2 * p + 3;
            gemmo_issue_loads(sb, (uint32_t)(c0 & 3) * GO_STAGE, tid, m0, n0,
                              c0 * BK2, Ah, Al, Bh);
            CP_COMMIT();
            gemmo_issue_loads(sb, (uint32_t)(c1 & 3) * GO_STAGE, tid, m0, n0,
                              c1 * BK2, Ah, Al, Bh);
            CP_COMMIT();
        }
        gemmo_compute_chunk(sb, (uint32_t)((2 * p) & 3) * GO_STAGE,
                            lane, wm, wn, c);
        gemmo_compute_chunk(sb, (uint32_t)((2 * p + 1) & 3) * GO_STAGE,
                            lane, wm, wn, c);
    }

#pragma unroll
    for (int mt = 0; mt < 2; mt++) {
        const int mrow = m0 + wm * 32 + mt * 16 + (lane >> 2);
#pragma unroll
        for (int nt = 0; nt < 4; nt++) {
            const int ncol = n0 + wn * 32 + nt * 8 + (lane & 3) * 2;
            const float b0 = bias[ncol], b1 = bias[ncol + 1];
            float2 o0 = make_float2(c[mt][nt][0] + b0, c[mt][nt][1] + b1);
            float2 o1 = make_float2(c[mt][nt][2] + b0, c[mt][nt][3] + b1);
            *reinterpret_cast<float2*>(&Cf[(size_t)mrow * D_MODEL + ncol]) = o0;
            *reinterpret_cast<float2*>(&Cf[(size_t)(mrow + 8) * D_MODEL + ncol]) = o1;
        }
    }
}

// ===========================================================================
// fp16 flash attention: BQ=128, 256 thr. Q hi/lo; K,V single fp16.
// S = QhK + QlK; ctx = PhV + PlV. exp2-domain softmax.
// 4-stage ring, TWO 64-key tiles per barrier (16 barriers total).
// smem: Q (hi+lo) 36864 + 4 stages x (KH|VH = 18432) = 110592 B.
// ===========================================================================
#define AT_LD 72
#define A_QH 0
#define A_QL 18432
#define A_QSZ 36864
#define A_KH 0
#define A_VH 9216
#define A_STAGE 18432
#define A_SM_TOTAL (A_QSZ + 4 * A_STAGE)   // 110592

__device__ __forceinline__ void attn_issue_loads(
    uint32_t sb, uint32_t stg, int tid, size_t rbase, int kt, int hcol,
    const __half* Kh, const __half* Vh)
{
    const int r  = tid >> 3;
    const int c8 = (tid & 7) * 8;
#pragma unroll
    for (int it = 0; it < 2; it++) {
        const int rr = r + it * 32;
        const size_t g = (rbase + kt + rr) * D_MODEL + hcol + c8;
        const uint32_t so = (uint32_t)(rr * AT_LD + c8) * 2;
        cp_async16(sb + stg + A_KH + so, &Kh[g]);
        cp_async16(sb + stg + A_VH + so, &Vh[g]);
    }
}

__global__ __launch_bounds__(256, 2) void attn_hmma_kernel(
    const __half* __restrict__ Qh, const __half* __restrict__ Ql,
    const __half* __restrict__ Kh, const __half* __restrict__ Vh,
    __half* __restrict__ Ch, __half* __restrict__ Cl)
{
    extern __shared__ char sma[];
    const uint32_t sb = smem_to_u32(sma);
    const int tid  = threadIdx.x;
    const int lane = tid & 31;
    const int w    = tid >> 5;
    const int q0   = blockIdx.x * 128;
    const int h    = blockIdx.y;
    const int b    = blockIdx.z;
    const int hcol = h * HD;
    const size_t rbase = (size_t)b * S_LEN;

    const int l_row = lane & 15;
    const int l_c8  = (lane >> 4) * 8;

    // Prologue: prefetch K/V tiles 0 and 1 (pair 0)
    attn_issue_loads(sb, A_QSZ + 0 * A_STAGE, tid, rbase, 0 * 64, hcol, Kh, Vh);
    CP_COMMIT();
    attn_issue_loads(sb, A_QSZ + 1 * A_STAGE, tid, rbase, 1 * 64, hcol, Kh, Vh);
    CP_COMMIT();

    // Q tile (regular stores; visible after first in-loop syncthreads)
    {
        const int r = tid >> 3;
        const int c8 = (tid & 7) * 8;
#pragma unroll
        for (int it = 0; it < 4; it++) {
            const int rr = r + it * 32;
            const size_t g = (rbase + q0 + rr) * D_MODEL + hcol + c8;
            *reinterpret_cast<uint4*>(sma + A_QH + (rr * AT_LD + c8) * 2) =
                *reinterpret_cast<const uint4*>(&Qh[g]);
            *reinterpret_cast<uint4*>(sma + A_QL + (rr * AT_LD + c8) * 2) =
                *reinterpret_cast<const uint4*>(&Ql[g]);
        }
    }

    float ctx[8][4];
#pragma unroll
    for (int nt = 0; nt < 8; nt++)
#pragma unroll
        for (int j = 0; j < 4; j++) ctx[nt][j] = 0.0f;
    float m0r = -INFINITY, m1r = -INFINITY, l0r = 0.0f, l1r = 0.0f;

    const int NPT = (S_LEN / 64) / 2;   // 16 pairs of key tiles
    for (int p = 0; p < NPT; p++) {
        CP_WAIT0();
        __syncthreads();
        if (p + 1 < NPT) {
            const int t0 = 2 * p + 2, t1 = 2 * p + 3;
            attn_issue_loads(sb, A_QSZ + (uint32_t)(t0 & 3) * A_STAGE,
                             tid, rbase, t0 * 64, hcol, Kh, Vh);
            CP_COMMIT();
            attn_issue_loads(sb, A_QSZ + (uint32_t)(t1 & 3) * A_STAGE,
                             tid, rbase, t1 * 64, hcol, Kh, Vh);
            CP_COMMIT();
        }

#pragma unroll
        for (int half = 0; half < 2; half++) {
            const int ti = 2 * p + half;
            const uint32_t cur = A_QSZ + (uint32_t)(ti & 3) * A_STAGE;

            // ---- S = Q K^T, 2-term split
            float S[8][4];
#pragma unroll
            for (int nt = 0; nt < 8; nt++)
#pragma unroll
                for (int j = 0; j < 4; j++) S[nt][j] = 0.0f;

#pragma unroll
            for (int ks = 0; ks < 4; ks++) {
                uint32_t qh[4], ql[4];
                const uint32_t qoff =
                    ((w * 16 + l_row) * AT_LD + ks * 16 + l_c8) * 2;
                ldsm_x4(qh, sb + A_QH + qoff);
                ldsm_x4(ql, sb + A_QL + qoff);
#pragma unroll
                for (int g = 0; g < 4; g++) {
                    uint32_t kh[4];
                    const uint32_t koff = cur + A_KH +
                        ((g * 16 + l_row) * AT_LD + ks * 16 + l_c8) * 2;
                    ldsm_x4(kh, sb + koff);
                    mma_f16(S[2 * g],     qh, kh[0], kh[2]);
                    mma_f16(S[2 * g + 1], qh, kh[1], kh[3]);
                    mma_f16(S[2 * g],     ql, kh[0], kh[2]);
                    mma_f16(S[2 * g + 1], ql, kh[1], kh[3]);
                }
            }

            // ---- online softmax (exp2 domain)
            float mx0 = -INFINITY, mx1 = -INFINITY;
#pragma unroll
            for (int nt = 0; nt < 8; nt++) {
                mx0 = fmaxf(mx0, fmaxf(S[nt][0], S[nt][1]));
                mx1 = fmaxf(mx1, fmaxf(S[nt][2], S[nt][3]));
            }
            mx0 = fmaxf(mx0, __shfl_xor_sync(0xffffffffu, mx0, 1));
            mx0 = fmaxf(mx0, __shfl_xor_sync(0xffffffffu, mx0, 2));
            mx1 = fmaxf(mx1, __shfl_xor_sync(0xffffffffu, mx1, 1));
            mx1 = fmaxf(mx1, __shfl_xor_sync(0xffffffffu, mx1, 2));
            const float mn0 = fmaxf(m0r, mx0);
            const float mn1 = fmaxf(m1r, mx1);
            const float cr0 = exp2f(m0r - mn0);
            const float cr1 = exp2f(m1r - mn1);
            float s0 = 0.0f, s1 = 0.0f;
#pragma unroll
            for (int nt = 0; nt < 8; nt++) {
                S[nt][0] = exp2f(S[nt][0] - mn0);
                S[nt][1] = exp2f(S[nt][1] - mn0);
                S[nt][2] = exp2f(S[nt][2] - mn1);
                S[nt][3] = exp2f(S[nt][3] - mn1);
                s0 += S[nt][0] + S[nt][1];
                s1 += S[nt][2] + S[nt][3];
                ctx[nt][0] *= cr0; ctx[nt][1] *= cr0;
                ctx[nt][2] *= cr1; ctx[nt][3] *= cr1;
            }
            s0 += __shfl_xor_sync(0xffffffffu, s0, 1);
            s0 += __shfl_xor_sync(0xffffffffu, s0, 2);
            s1 += __shfl_xor_sync(0xffffffffu, s1, 1);
            s1 += __shfl_xor_sync(0xffffffffu, s1, 2);
            l0r = l0r * cr0 + s0;
            l1r = l1r * cr1 + s1;
            m0r = mn0;
            m1r = mn1;

            // ---- pack P into a-frags (hi + lo, fp16)
            uint32_t ph[4][4], pl[4][4];
#pragma unroll
            for (int j = 0; j < 4; j++) {
                const float p0 = S[2 * j][0],     p1 = S[2 * j][1];
                const float p2 = S[2 * j][2],     p3 = S[2 * j][3];
                const float p4 = S[2 * j + 1][0], p5 = S[2 * j + 1][1];
                const float p6 = S[2 * j + 1][2], p7 = S[2 * j + 1][3];
                ph[j][0] = cvt_f16x2(p0, p1);
                ph[j][1] = cvt_f16x2(p2, p3);
                ph[j][2] = cvt_f16x2(p4, p5);
                ph[j][3] = cvt_f16x2(p6, p7);
                pl[j][0] = cvt_f16x2(p0 - h_rt(p0), p1 - h_rt(p1));
                pl[j][1] = cvt_f16x2(p2 - h_rt(p2), p3 - h_rt(p3));
                pl[j][2] = cvt_f16x2(p4 - h_rt(p4), p5 - h_rt(p5));
                pl[j][3] = cvt_f16x2(p6 - h_rt(p6), p7 - h_rt(p7));
            }

            // ---- ctx += P V, 2-term
#pragma unroll
            for (int kc = 0; kc < 4; kc++) {
#pragma unroll
                for (int dg = 0; dg < 4; dg++) {
                    uint32_t vh[4];
                    const uint32_t voff = cur + A_VH +
                        ((kc * 16 + l_row) * AT_LD + dg * 16 + l_c8) * 2;
                    ldsm_x4_t(vh, sb + voff);
                    mma_f16(ctx[2 * dg],     ph[kc], vh[0], vh[1]);
                    mma_f16(ctx[2 * dg + 1], ph[kc], vh[2], vh[3]);
                    mma_f16(ctx[2 * dg],     pl[kc], vh[0], vh[1]);
                    mma_f16(ctx[2 * dg + 1], pl[kc], vh[2], vh[3]);
                }
            }
        }
    }

    // ---- epilogue: normalize, split, store ctx hi/lo (fp16)
    const float inv0 = 1.0f / l0r;
    const float inv1 = 1.0f / l1r;
    const int row0 = q0 + w * 16 + (lane >> 2);
#pragma unroll
    for (int nt = 0; nt < 8; nt++) {
        const int col = hcol + nt * 8 + (lane & 3) * 2;
        const float v00 = ctx[nt][0] * inv0, v01 = ctx[nt][1] * inv0;
        const float v10 = ctx[nt][2] * inv1, v11 = ctx[nt][3] * inv1;
        const size_t g0 = (rbase + row0) * D_MODEL + col;
        const size_t g1 = (rbase + row0 + 8) * D_MODEL + col;
        *reinterpret_cast<uint32_t*>(&Ch[g0]) = cvt_f16x2(v00, v01);
        *reinterpret_cast<uint32_t*>(&Ch[g1]) = cvt_f16x2(v10, v11);
        *reinterpret_cast<uint32_t*>(&Cl[g0]) =
            cvt_f16x2(v00 - h_rt(v00), v01 - h_rt(v01));
        *reinterpret_cast<uint32_t*>(&Cl[g1]) =
            cvt_f16x2(v10 - h_rt(v10), v11 - h_rt(v11));
    }
}

// ---------------------------------------------------------------------------
// Launch
// ---------------------------------------------------------------------------
extern "C" void kernel_launch(void* const* d_in, const int* in_sizes, int n_in,
                              void* d_out, int out_size)
{
    const float* x  = (const float*)d_in[0];
    const float* Wq = (const float*)d_in[1];
    const float* bq = (const float*)d_in[2];
    const float* Wk = (const float*)d_in[3];
    const float* bk = (const float*)d_in[4];
    const float* Wv = (const float*)d_in[5];
    const float* bv = (const float*)d_in[6];
    const float* Wo = (const float*)d_in[7];
    const float* bo = (const float*)d_in[8];
    float* out = (float*)d_out;

    __half *xh, *xl, *wh, *qh, *ql, *kh, *vh, *ch, *cl;
    cudaGetSymbolAddress((void**)&xh, g_xh);
    cudaGetSymbolAddress((void**)&xl, g_xl);
    cudaGetSymbolAddress((void**)&wh, g_wh);
    cudaGetSymbolAddress((void**)&qh, g_qh);
    cudaGetSymbolAddress((void**)&ql, g_ql);
    cudaGetSymbolAddress((void**)&kh, g_kh);
    cudaGetSymbolAddress((void**)&vh, g_vh);
    cudaGetSymbolAddress((void**)&ch, g_ch);
    cudaGetSymbolAddress((void**)&cl, g_cl);

    cudaFuncSetAttribute(gemm_qkv_kernel,
                         cudaFuncAttributeMaxDynamicSharedMemorySize,
                         SM_G2_TOTAL);
    cudaFuncSetAttribute(gemm_o_kernel,
                         cudaFuncAttributeMaxDynamicSharedMemorySize,
                         SM_GO_TOTAL);
    cudaFuncSetAttribute(attn_hmma_kernel,
                         cudaFuncAttributeMaxDynamicSharedMemorySize,
                         A_SM_TOTAL);

    dim3 split_grid((M_ROWS * D_MODEL / 16 + 255) / 256, 5);
    split_all_kernel<<<split_grid, 256>>>(x, Wq, Wk, Wv, Wo, xh, xl, wh);

    dim3 qkv_grid(M_ROWS / BM2, D_MODEL / BN2, 3);   // 32 x 6 x 3 = 576
    gemm_qkv_kernel<<<qkv_grid, 256, SM_G2_TOTAL>>>(
        xh, xl, wh, bq, bk, bv, qh, ql, kh, vh);

    dim3 attn_grid(S_LEN / 128, H_NUM, B_SZ);        // 16 x 12 x 2 = 384
    attn_hmma_kernel<<<attn_grid, 256, A_SM_TOTAL>>>(
        qh, ql, kh, vh, ch, cl);

    dim3 o_grid(M_ROWS / 64, D_MODEL / 128);         // 64 x 6 = 384
    gemm_o_kernel<<<o_grid, 256, SM_GO_TOTAL>>>(
        ch, cl, wh + 3 * W_ELEMS, bo, out);
}

// round 16
// speedup vs baseline: 1.5612x; 1.0053x over previous
#include <cuda_runtime.h>
#include <cuda_fp16.h>
#include <cstdint>
#include <math.h>

// Problem constants
#define S_LEN   2048
#define D_MODEL 768
#define H_NUM   12
#define HD      64
#define B_SZ    2
#define M_ROWS  (B_SZ * S_LEN)   // 4096
#define W_ELEMS (D_MODEL * D_MODEL)

// Q pre-scale: 1/sqrt(64) * log2(e)  (softmax done in exp2 domain)
#define ALPHA_Q (0.125f * 1.44269504088896f)

// Scratch (allocation-free rule: __device__ globals). fp16.
// A-side tensors (x, q, ctx) keep hi/lo; B-side (W, k, v) single fp16.
__device__ __half g_xh[M_ROWS * D_MODEL];
__device__ __half g_xl[M_ROWS * D_MODEL];
__device__ __half g_wh[4 * W_ELEMS];
__device__ __half g_qh[M_ROWS * D_MODEL];
__device__ __half g_ql[M_ROWS * D_MODEL];
__device__ __half g_kh[M_ROWS * D_MODEL];
__device__ __half g_vh[M_ROWS * D_MODEL];
__device__ __half g_ch[M_ROWS * D_MODEL];
__device__ __half g_cl[M_ROWS * D_MODEL];

// ===========================================================================
// Warp-MMA + async-copy helpers
// ===========================================================================
__device__ __forceinline__ uint32_t smem_to_u32(const void* p) {
    uint32_t a;
    asm("{ .reg .u64 t; cvta.to.shared.u64 t, %1; cvt.u32.u64 %0, t; }"
        : "=r"(a) : "l"(p));
    return a;
}
__device__ __forceinline__ void ldsm_x4(uint32_t* r, uint32_t addr) {
    asm volatile(
        "ldmatrix.sync.aligned.m8n8.x4.shared.b16 {%0,%1,%2,%3}, [%4];"
        : "=r"(r[0]), "=r"(r[1]), "=r"(r[2]), "=r"(r[3]) : "r"(addr));
}
__device__ __forceinline__ void ldsm_x4_t(uint32_t* r, uint32_t addr) {
    asm volatile(
        "ldmatrix.sync.aligned.m8n8.x4.trans.shared.b16 {%0,%1,%2,%3}, [%4];"
        : "=r"(r[0]), "=r"(r[1]), "=r"(r[2]), "=r"(r[3]) : "r"(addr));
}
__device__ __forceinline__ void mma_f16(float* c, const uint32_t* a,
                                        uint32_t b0, uint32_t b1) {
    asm volatile(
        "mma.sync.aligned.m16n8k16.row.col.f32.f16.f16.f32 "
        "{%0,%1,%2,%3}, {%4,%5,%6,%7}, {%8,%9}, {%0,%1,%2,%3};"
        : "+f"(c[0]), "+f"(c[1]), "+f"(c[2]), "+f"(c[3])
        : "r"(a[0]), "r"(a[1]), "r"(a[2]), "r"(a[3]), "r"(b0), "r"(b1));
}
// pack two floats into f16x2; first arg = lower-address element
__device__ __forceinline__ uint32_t cvt_f16x2(float lo, float hi) {
    uint32_t r;
    asm("cvt.rn.f16x2.f32 %0, %1, %2;" : "=r"(r) : "f"(hi), "f"(lo));
    return r;
}
__device__ __forceinline__ float h_rt(float x) {
    return __half2float(__float2half_rn(x));
}
__device__ __forceinline__ void cp_async16(uint32_t dst, const void* src) {
    asm volatile("cp.async.cg.shared.global [%0], [%1], 16;"
                 :: "r"(dst), "l"(src) : "memory");
}
#define CP_COMMIT() asm volatile("cp.async.commit_group;" ::: "memory")
#define CP_WAIT1()  asm volatile("cp.async.wait_group 1;" ::: "memory")
#define CP_WAIT0()  asm volatile("cp.async.wait_group 0;" ::: "memory")

// ===========================================================================
// Fused split: x -> (fp16 hi, fp16 lo); weights -> fp16 hi only.
// Each thread handles 4 strided float4s (MLP=4; splits were latency-bound).
// ===========================================================================
__global__ __launch_bounds__(256) void split_all_kernel(
    const float* __restrict__ x,
    const float* __restrict__ Wq, const float* __restrict__ Wk,
    const float* __restrict__ Wv, const float* __restrict__ Wo,
    __half* __restrict__ xh, __half* __restrict__ xl,
    __half* __restrict__ wh)
{
    const int t = blockIdx.y;
    const float* src;
    __half *hi, *lo = nullptr;
    int n4;
    if (t == 0) { src = x;  hi = xh; lo = xl; n4 = M_ROWS * D_MODEL / 4; }
    else {
        const float* ws[4] = {Wq, Wk, Wv, Wo};
        src = ws[t - 1];
        hi = wh + (size_t)(t - 1) * W_ELEMS;
        n4 = W_ELEMS / 4;
    }
    const int q = n4 >> 2;   // quarter stride
    const int i0 = blockIdx.x * blockDim.x + threadIdx.x;
    if (i0 >= q) return;
#pragma unroll
    for (int it = 0; it < 4; it++) {
        const int i = i0 + it * q;
        float4 v = reinterpret_cast<const float4*>(src)[i];
        uint32_t* hp = reinterpret_cast<uint32_t*>(hi) + 2 * i;
        hp[0] = cvt_f16x2(v.x, v.y);
        hp[1] = cvt_f16x2(v.z, v.w);
        if (lo) {
            uint32_t* lp = reinterpret_cast<uint32_t*>(lo) + 2 * i;
            lp[0] = cvt_f16x2(v.x - h_rt(v.x), v.y - h_rt(v.y));
            lp[1] = cvt_f16x2(v.z - h_rt(v.z), v.w - h_rt(v.w));
        }
    }
}

// ===========================================================================
// QKV GEMM: CTA tile 128x128, BK=32, 256 thr, 8 warps 4(M)x2(N), warp 32x64.
// Two-pass MMA order (hh x16, lh x16). B single fp16.
// 3-stage cp.async, single sync per chunk.
// Stage: AH|AL (128x40 f16 ea = 10240 B) + BH (32x136 f16 = 8704 B) = 29184 B.
// ===========================================================================
#define BM2 128
#define BN2 128
#define BK2 32
#define LDA2 40
#define LDB2 136
#define G2_AH 0
#define G2_AL 10240
#define G2_BH 20480
#define G2_STAGE 29184
#define SM_G2_TOTAL (3 * G2_STAGE)   // 87552
#define NCH2 (D_MODEL / BK2)         // 24

__device__ __forceinline__ void gemm2_issue_loads(
    uint32_t sb, uint32_t stg, int tid, int m0, int n0, int k0,
    const __half* Ah, const __half* Al, const __half* Bh)
{
#pragma unroll
    for (int it = 0; it < 2; it++) {
        const int idx = tid + it * 256;
        // A: 128 rows x 32 k -> 512 uint4
        {
            const int r = idx >> 2, c8 = (idx & 3) * 8;
            const size_t g = (size_t)(m0 + r) * D_MODEL + k0 + c8;
            const uint32_t so = (uint32_t)(r * LDA2 + c8) * 2;
            cp_async16(sb + stg + G2_AH + so, &Ah[g]);
            cp_async16(sb + stg + G2_AL + so, &Al[g]);
        }
        // B: 32 k x 128 n -> 512 uint4
        {
            const int r = idx >> 4, n8 = (idx & 15) * 8;
            const size_t g = (size_t)(k0 + r) * D_MODEL + n0 + n8;
            const uint32_t so = (uint32_t)(r * LDB2 + n8) * 2;
            cp_async16(sb + stg + G2_BH + so, &Bh[g]);
        }
    }
}

__device__ __forceinline__ void gemm2_compute_chunk(
    uint32_t sb, uint32_t stg, int lane, int wm, int wn, float c[2][8][4])
{
    const int a_row = lane & 15;
    const int a_kc  = (lane >> 4) * 8;
    const int b_k   = lane & 15;
    const int b_n   = (lane >> 4) * 8;
#pragma unroll
    for (int ks = 0; ks < BK2 / 16; ks++) {
        uint32_t ah0[4], ah1[4], al0[4], al1[4];
        {
            const uint32_t offH = stg + G2_AH +
                ((wm * 32 + a_row) * LDA2 + ks * 16 + a_kc) * 2;
            ldsm_x4(ah0, sb + offH);
            ldsm_x4(ah1, sb + offH + 16 * LDA2 * 2);
            const uint32_t offL = stg + G2_AL +
                ((wm * 32 + a_row) * LDA2 + ks * 16 + a_kc) * 2;
            ldsm_x4(al0, sb + offL);
            ldsm_x4(al1, sb + offL + 16 * LDA2 * 2);
        }
        uint32_t bh[4][4];
#pragma unroll
        for (int nb = 0; nb < 4; nb++) {
            const uint32_t offB = stg + G2_BH +
                ((ks * 16 + b_k) * LDB2 + wn * 64 + nb * 16 + b_n) * 2;
            ldsm_x4_t(bh[nb], sb + offB);
        }
        // Pass 1: hi*hi — 16 MMAs, distinct accumulators
#pragma unroll
        for (int nb = 0; nb < 4; nb++) {
            mma_f16(c[0][2 * nb],     ah0, bh[nb][0], bh[nb][1]);
            mma_f16(c[1][2 * nb],     ah1, bh[nb][0], bh[nb][1]);
            mma_f16(c[0][2 * nb + 1], ah0, bh[nb][2], bh[nb][3]);
            mma_f16(c[1][2 * nb + 1], ah1, bh[nb][2], bh[nb][3]);
        }
        // Pass 2: lo*hi — 16 MMAs
#pragma unroll
        for (int nb = 0; nb < 4; nb++) {
            mma_f16(c[0][2 * nb],     al0, bh[nb][0], bh[nb][1]);
            mma_f16(c[1][2 * nb],     al1, bh[nb][0], bh[nb][1]);
            mma_f16(c[0][2 * nb + 1], al0, bh[nb][2], bh[nb][3]);
            mma_f16(c[1][2 * nb + 1], al1, bh[nb][2], bh[nb][3]);
        }
    }
}

// blockIdx.z: 0 -> Q (hi/lo, *ALPHA_Q), 1 -> K (single), 2 -> V (single)
__global__ __launch_bounds__(256, 2) void gemm_qkv_kernel(
    const __half* __restrict__ Ah, const __half* __restrict__ Al,
    const __half* __restrict__ whb,
    const float* __restrict__ bq, const float* __restrict__ bk,
    const float* __restrict__ bv,
    __half* __restrict__ qh, __half* __restrict__ ql,
    __half* __restrict__ kh, __half* __restrict__ vh)
{
    extern __shared__ char smg[];
    const uint32_t sb = smem_to_u32(smg);
    const int tid  = threadIdx.x;
    const int lane = tid & 31;
    const int w    = tid >> 5;
    const int wm   = w & 3;
    const int wn   = w >> 2;
    const int m0   = blockIdx.x * BM2;
    const int n0   = blockIdx.y * BN2;
    const int z    = blockIdx.z;

    const __half* Bh = whb + (size_t)z * W_ELEMS;
    const float* bias = (z == 0) ? bq : (z == 1) ? bk : bv;
    const float alpha = (z == 0) ? ALPHA_Q : 1.0f;
    __half* Ch = (z == 0) ? qh : (z == 1) ? kh : vh;

    float c[2][8][4];
#pragma unroll
    for (int mt = 0; mt < 2; mt++)
#pragma unroll
        for (int nt = 0; nt < 8; nt++)
#pragma unroll
            for (int j = 0; j < 4; j++) c[mt][nt][j] = 0.0f;

    // Prologue: prefetch chunks 0 and 1
    gemm2_issue_loads(sb, 0 * G2_STAGE, tid, m0, n0, 0 * BK2, Ah, Al, Bh);
    CP_COMMIT();
    gemm2_issue_loads(sb, 1 * G2_STAGE, tid, m0, n0, 1 * BK2, Ah, Al, Bh);
    CP_COMMIT();

    int s_cur = 0, s_nxt = 2;
    for (int ch = 0; ch < NCH2; ch++) {
        if (ch == NCH2 - 1) { CP_WAIT0(); } else { CP_WAIT1(); }
        __syncthreads();
        if (ch + 2 < NCH2) {
            gemm2_issue_loads(sb, s_nxt * G2_STAGE, tid, m0, n0,
                              (ch + 2) * BK2, Ah, Al, Bh);
            CP_COMMIT();
        }
        gemm2_compute_chunk(sb, s_cur * G2_STAGE, lane, wm, wn, c);
        s_cur = (s_cur == 2) ? 0 : s_cur + 1;
        s_nxt = (s_nxt == 2) ? 0 : s_nxt + 1;
    }

#pragma unroll
    for (int mt = 0; mt < 2; mt++) {
        const int mrow = m0 + wm * 32 + mt * 16 + (lane >> 2);
#pragma unroll
        for (int nt = 0; nt < 8; nt++) {
            const int ncol = n0 + wn * 64 + nt * 8 + (lane & 3) * 2;
            const float b0 = bias[ncol], b1 = bias[ncol + 1];
            const float v00 = alpha * (c[mt][nt][0] + b0);
            const float v01 = alpha * (c[mt][nt][1] + b1);
            const float v10 = alpha * (c[mt][nt][2] + b0);
            const float v11 = alpha * (c[mt][nt][3] + b1);
            const size_t g0 = (size_t)mrow * D_MODEL + ncol;
            const size_t g1 = (size_t)(mrow + 8) * D_MODEL + ncol;
            *reinterpret_cast<uint32_t*>(&Ch[g0]) = cvt_f16x2(v00, v01);
            *reinterpret_cast<uint32_t*>(&Ch[g1]) = cvt_f16x2(v10, v11);
            if (z == 0) {
                *reinterpret_cast<uint32_t*>(&ql[g0]) =
                    cvt_f16x2(v00 - h_rt(v00), v01 - h_rt(v01));
                *reinterpret_cast<uint32_t*>(&ql[g1]) =
                    cvt_f16x2(v10 - h_rt(v10), v11 - h_rt(v11));
            }
        }
    }
}

// ===========================================================================
// O-projection GEMM (R14 config — measured best at 43.1 us):
// BM=64 x BN=128, 256 thr, 8 warps 2(M)x4(N), warp 32x32. fp32 output.
// 3-stage, single chunk per barrier. Stage: AH|AL (5120 ea) + BH (8704) = 18944.
// ===========================================================================
#define GO_AH 0
#define GO_AL 5120
#define GO_BH 10240
#define GO_STAGE 18944
#define SM_GO_TOTAL (3 * GO_STAGE)   // 56832

__device__ __forceinline__ void gemmo_issue_loads(
    uint32_t sb, uint32_t stg, int tid, int m0, int n0, int k0,
    const __half* Ah, const __half* Al, const __half* Bh)
{
    // A: 64 rows x 32 k -> 256 uint4; 1 per thread
    {
        const int r = tid >> 2, c8 = (tid & 3) * 8;
        const size_t g = (size_t)(m0 + r) * D_MODEL + k0 + c8;
        const uint32_t so = (uint32_t)(r * LDA2 + c8) * 2;
        cp_async16(sb + stg + GO_AH + so, &Ah[g]);
        cp_async16(sb + stg + GO_AL + so, &Al[g]);
    }
    // B: 32 k x 128 n -> 512 uint4; 2 per thread
#pragma unroll
    for (int it = 0; it < 2; it++) {
        const int idx = tid + it * 256;
        const int r = idx >> 4, n8 = (idx & 15) * 8;
        const size_t g = (size_t)(k0 + r) * D_MODEL + n0 + n8;
        const uint32_t so = (uint32_t)(r * LDB2 + n8) * 2;
        cp_async16(sb + stg + GO_BH + so, &Bh[g]);
    }
}

__global__ __launch_bounds__(256, 2) void gemm_o_kernel(
    const __half* __restrict__ Ah, const __half* __restrict__ Al,
    const __half* __restrict__ Bh,
    const float* __restrict__ bias, float* __restrict__ Cf)
{
    extern __shared__ char smg[];
    const uint32_t sb = smem_to_u32(smg);
    const int tid  = threadIdx.x;
    const int lane = tid & 31;
    const int w    = tid >> 5;
    const int wm   = w & 1;
    const int wn   = w >> 1;
    const int m0   = blockIdx.x * 64;
    const int n0   = blockIdx.y * 128;

    const int a_row = lane & 15;
    const int a_kc  = (lane >> 4) * 8;
    const int b_k   = lane & 15;
    const int b_n   = (lane >> 4) * 8;

    float c[2][4][4];
#pragma unroll
    for (int mt = 0; mt < 2; mt++)
#pragma unroll
        for (int nt = 0; nt < 4; nt++)
#pragma unroll
            for (int j = 0; j < 4; j++) c[mt][nt][j] = 0.0f;

    gemmo_issue_loads(sb, 0 * GO_STAGE, tid, m0, n0, 0 * BK2, Ah, Al, Bh);
    CP_COMMIT();
    gemmo_issue_loads(sb, 1 * GO_STAGE, tid, m0, n0, 1 * BK2, Ah, Al, Bh);
    CP_COMMIT();

    int s_cur = 0, s_nxt = 2;
    for (int ch = 0; ch < NCH2; ch++) {
        if (ch == NCH2 - 1) { CP_WAIT0(); } else { CP_WAIT1(); }
        __syncthreads();
        if (ch + 2 < NCH2) {
            gemmo_issue_loads(sb, s_nxt * GO_STAGE, tid, m0, n0,
                              (ch + 2) * BK2, Ah, Al, Bh);
            CP_COMMIT();
        }
        const uint32_t cur = s_cur * GO_STAGE;

#pragma unroll
        for (int ks = 0; ks < BK2 / 16; ks++) {
            uint32_t ah0[4], ah1[4], al0[4], al1[4];
            {
                const uint32_t offH = cur + GO_AH +
                    ((wm * 32 + a_row) * LDA2 + ks * 16 + a_kc) * 2;
                ldsm_x4(ah0, sb + offH);
                ldsm_x4(ah1, sb + offH + 16 * LDA2 * 2);
                const uint32_t offL = cur + GO_AL +
                    ((wm * 32 + a_row) * LDA2 + ks * 16 + a_kc) * 2;
                ldsm_x4(al0, sb + offL);
                ldsm_x4(al1, sb + offL + 16 * LDA2 * 2);
            }
            uint32_t bh[2][4];
#pragma unroll
            for (int nb = 0; nb < 2; nb++) {
                const uint32_t offB = cur + GO_BH +
                    ((ks * 16 + b_k) * LDB2 + wn * 32 + nb * 16 + b_n) * 2;
                ldsm_x4_t(bh[nb], sb + offB);
            }
#pragma unroll
            for (int nb = 0; nb < 2; nb++) {
                mma_f16(c[0][2 * nb],     ah0, bh[nb][0], bh[nb][1]);
                mma_f16(c[1][2 * nb],     ah1, bh[nb][0], bh[nb][1]);
                mma_f16(c[0][2 * nb + 1], ah0, bh[nb][2], bh[nb][3]);
                mma_f16(c[1][2 * nb + 1], ah1, bh[nb][2], bh[nb][3]);
            }
#pragma unroll
            for (int nb = 0; nb < 2; nb++) {
                mma_f16(c[0][2 * nb],     al0, bh[nb][0], bh[nb][1]);
                mma_f16(c[1][2 * nb],     al1, bh[nb][0], bh[nb][1]);
                mma_f16(c[0][2 * nb + 1], al0, bh[nb][2], bh[nb][3]);
                mma_f16(c[1][2 * nb + 1], al1, bh[nb][2], bh[nb][3]);
            }
        }
        s_cur = (s_cur == 2) ? 0 : s_cur + 1;
        s_nxt = (s_nxt == 2) ? 0 : s_nxt + 1;
    }

#pragma unroll
    for (int mt = 0; mt < 2; mt++) {
        const int mrow = m0 + wm * 32 + mt * 16 + (lane >> 2);
#pragma unroll
        for (int nt = 0; nt < 4; nt++) {
            const int ncol = n0 + wn * 32 + nt * 8 + (lane & 3) * 2;
            const float b0 = bias[ncol], b1 = bias[ncol + 1];
            float2 o0 = make_float2(c[mt][nt][0] + b0, c[mt][nt][1] + b1);
            float2 o1 = make_float2(c[mt][nt][2] + b0, c[mt][nt][3] + b1);
            *reinterpret_cast<float2*>(&Cf[(size_t)mrow * D_MODEL + ncol]) = o0;
            *reinterpret_cast<float2*>(&Cf[(size_t)(mrow + 8) * D_MODEL + ncol]) = o1;
        }
    }
}

// ===========================================================================
// fp16 flash attention (R15 config — measured winner): BQ=128, 256 thr.
// Q hi/lo; K,V single fp16. S = QhK + QlK; ctx = PhV + PlV. exp2 softmax.
// 4-stage ring, TWO 64-key tiles per barrier (16 barriers total).
// smem: Q (hi+lo) 36864 + 4 stages x (KH|VH = 18432) = 110592 B.
// ===========================================================================
#define AT_LD 72
#define A_QH 0
#define A_QL 18432
#define A_QSZ 36864
#define A_KH 0
#define A_VH 9216
#define A_STAGE 18432
#define A_SM_TOTAL (A_QSZ + 4 * A_STAGE)   // 110592

__device__ __forceinline__ void attn_issue_loads(
    uint32_t sb, uint32_t stg, int tid, size_t rbase, int kt, int hcol,
    const __half* Kh, const __half* Vh)
{
    const int r  = tid >> 3;
    const int c8 = (tid & 7) * 8;
#pragma unroll
    for (int it = 0; it < 2; it++) {
        const int rr = r + it * 32;
        const size_t g = (rbase + kt + rr) * D_MODEL + hcol + c8;
        const uint32_t so = (uint32_t)(rr * AT_LD + c8) * 2;
        cp_async16(sb + stg + A_KH + so, &Kh[g]);
        cp_async16(sb + stg + A_VH + so, &Vh[g]);
    }
}

__global__ __launch_bounds__(256, 2) void attn_hmma_kernel(
    const __half* __restrict__ Qh, const __half* __restrict__ Ql,
    const __half* __restrict__ Kh, const __half* __restrict__ Vh,
    __half* __restrict__ Ch, __half* __restrict__ Cl)
{
    extern __shared__ char sma[];
    const uint32_t sb = smem_to_u32(sma);
    const int tid  = threadIdx.x;
    const int lane = tid & 31;
    const int w    = tid >> 5;
    const int q0   = blockIdx.x * 128;
    const int h    = blockIdx.y;
    const int b    = blockIdx.z;
    const int hcol = h * HD;
    const size_t rbase = (size_t)b * S_LEN;

    const int l_row = lane & 15;
    const int l_c8  = (lane >> 4) * 8;

    // Prologue: prefetch K/V tiles 0 and 1 (pair 0)
    attn_issue_loads(sb, A_QSZ + 0 * A_STAGE, tid, rbase, 0 * 64, hcol, Kh, Vh);
    CP_COMMIT();
    attn_issue_loads(sb, A_QSZ + 1 * A_STAGE, tid, rbase, 1 * 64, hcol, Kh, Vh);
    CP_COMMIT();

    // Q tile (regular stores; visible after first in-loop syncthreads)
    {
        const int r = tid >> 3;
        const int c8 = (tid & 7) * 8;
#pragma unroll
        for (int it = 0; it < 4; it++) {
            const int rr = r + it * 32;
            const size_t g = (rbase + q0 + rr) * D_MODEL + hcol + c8;
            *reinterpret_cast<uint4*>(sma + A_QH + (rr * AT_LD + c8) * 2) =
                *reinterpret_cast<const uint4*>(&Qh[g]);
            *reinterpret_cast<uint4*>(sma + A_QL + (rr * AT_LD + c8) * 2) =
                *reinterpret_cast<const uint4*>(&Ql[g]);
        }
    }

    float ctx[8][4];
#pragma unroll
    for (int nt = 0; nt < 8; nt++)
#pragma unroll
        for (int j = 0; j < 4; j++) ctx[nt][j] = 0.0f;
    float m0r = -INFINITY, m1r = -INFINITY, l0r = 0.0f, l1r = 0.0f;

    const int NPT = (S_LEN / 64) / 2;   // 16 pairs of key tiles
    for (int p = 0; p < NPT; p++) {
        CP_WAIT0();
        __syncthreads();
        if (p + 1 < NPT) {
            const int t0 = 2 * p + 2, t1 = 2 * p + 3;
            attn_issue_loads(sb, A_QSZ + (uint32_t)(t0 & 3) * A_STAGE,
                             tid, rbase, t0 * 64, hcol, Kh, Vh);
            CP_COMMIT();
            attn_issue_loads(sb, A_QSZ + (uint32_t)(t1 & 3) * A_STAGE,
                             tid, rbase, t1 * 64, hcol, Kh, Vh);
            CP_COMMIT();
        }

#pragma unroll
        for (int half = 0; half < 2; half++) {
            const int ti = 2 * p + half;
            const uint32_t cur = A_QSZ + (uint32_t)(ti & 3) * A_STAGE;

            // ---- S = Q K^T, 2-term split
            float S[8][4];
#pragma unroll
            for (int nt = 0; nt < 8; nt++)
#pragma unroll
                for (int j = 0; j < 4; j++) S[nt][j] = 0.0f;

#pragma unroll
            for (int ks = 0; ks < 4; ks++) {
                uint32_t qh[4], ql[4];
                const uint32_t qoff =
                    ((w * 16 + l_row) * AT_LD + ks * 16 + l_c8) * 2;
                ldsm_x4(qh, sb + A_QH + qoff);
                ldsm_x4(ql, sb + A_QL + qoff);
#pragma unroll
                for (int g = 0; g < 4; g++) {
                    uint32_t kh[4];
                    const uint32_t koff = cur + A_KH +
                        ((g * 16 + l_row) * AT_LD + ks * 16 + l_c8) * 2;
                    ldsm_x4(kh, sb + koff);
                    mma_f16(S[2 * g],     qh, kh[0], kh[2]);
                    mma_f16(S[2 * g + 1], qh, kh[1], kh[3]);
                    mma_f16(S[2 * g],     ql, kh[0], kh[2]);
                    mma_f16(S[2 * g + 1], ql, kh[1], kh[3]);
                }
            }

            // ---- online softmax (exp2 domain)
            float mx0 = -INFINITY, mx1 = -INFINITY;
#pragma unroll
            for (int nt = 0; nt < 8; nt++) {
                mx0 = fmaxf(mx0, fmaxf(S[nt][0], S[nt][1]));
                mx1 = fmaxf(mx1, fmaxf(S[nt][2], S[nt][3]));
            }
            mx0 = fmaxf(mx0, __shfl_xor_sync(0xffffffffu, mx0, 1));
            mx0 = fmaxf(mx0, __shfl_xor_sync(0xffffffffu, mx0, 2));
            mx1 = fmaxf(mx1, __shfl_xor_sync(0xffffffffu, mx1, 1));
            mx1 = fmaxf(mx1, __shfl_xor_sync(0xffffffffu, mx1, 2));
            const float mn0 = fmaxf(m0r, mx0);
            const float mn1 = fmaxf(m1r, mx1);
            const float cr0 = exp2f(m0r - mn0);
            const float cr1 = exp2f(m1r - mn1);
            float s0 = 0.0f, s1 = 0.0f;
#pragma unroll
            for (int nt = 0; nt < 8; nt++) {
                S[nt][0] = exp2f(S[nt][0] - mn0);
                S[nt][1] = exp2f(S[nt][1] - mn0);
                S[nt][2] = exp2f(S[nt][2] - mn1);
                S[nt][3] = exp2f(S[nt][3] - mn1);
                s0 += S[nt][0] + S[nt][1];
                s1 += S[nt][2] + S[nt][3];
                ctx[nt][0] *= cr0; ctx[nt][1] *= cr0;
                ctx[nt][2] *= cr1; ctx[nt][3] *= cr1;
            }
            s0 += __shfl_xor_sync(0xffffffffu, s0, 1);
            s0 += __shfl_xor_sync(0xffffffffu, s0, 2);
            s1 += __shfl_xor_sync(0xffffffffu, s1, 1);
            s1 += __shfl_xor_sync(0xffffffffu, s1, 2);
            l0r = l0r * cr0 + s0;
            l1r = l1r * cr1 + s1;
            m0r = mn0;
            m1r = mn1;

            // ---- pack P into a-frags (hi + lo, fp16)
            uint32_t ph[4][4], pl[4][4];
#pragma unroll
            for (int j = 0; j < 4; j++) {
                const float p0 = S[2 * j][0],     p1 = S[2 * j][1];
                const float p2 = S[2 * j][2],     p3 = S[2 * j][3];
                const float p4 = S[2 * j + 1][0], p5 = S[2 * j + 1][1];
                const float p6 = S[2 * j + 1][2], p7 = S[2 * j + 1][3];
                ph[j][0] = cvt_f16x2(p0, p1);
                ph[j][1] = cvt_f16x2(p2, p3);
                ph[j][2] = cvt_f16x2(p4, p5);
                ph[j][3] = cvt_f16x2(p6, p7);
                pl[j][0] = cvt_f16x2(p0 - h_rt(p0), p1 - h_rt(p1));
                pl[j][1] = cvt_f16x2(p2 - h_rt(p2), p3 - h_rt(p3));
                pl[j][2] = cvt_f16x2(p4 - h_rt(p4), p5 - h_rt(p5));
                pl[j][3] = cvt_f16x2(p6 - h_rt(p6), p7 - h_rt(p7));
            }

            // ---- ctx += P V, 2-term
#pragma unroll
            for (int kc = 0; kc < 4; kc++) {
#pragma unroll
                for (int dg = 0; dg < 4; dg++) {
                    uint32_t vh[4];
                    const uint32_t voff = cur + A_VH +
                        ((kc * 16 + l_row) * AT_LD + dg * 16 + l_c8) * 2;
                    ldsm_x4_t(vh, sb + voff);
                    mma_f16(ctx[2 * dg],     ph[kc], vh[0], vh[1]);
                    mma_f16(ctx[2 * dg + 1], ph[kc], vh[2], vh[3]);
                    mma_f16(ctx[2 * dg],     pl[kc], vh[0], vh[1]);
                    mma_f16(ctx[2 * dg + 1], pl[kc], vh[2], vh[3]);
                }
            }
        }
    }

    // ---- epilogue: normalize, split, store ctx hi/lo (fp16)
    const float inv0 = 1.0f / l0r;
    const float inv1 = 1.0f / l1r;
    const int row0 = q0 + w * 16 + (lane >> 2);
#pragma unroll
    for (int nt = 0; nt < 8; nt++) {
        const int col = hcol + nt * 8 + (lane & 3) * 2;
        const float v00 = ctx[nt][0] * inv0, v01 = ctx[nt][1] * inv0;
        const float v10 = ctx[nt][2] * inv1, v11 = ctx[nt][3] * inv1;
        const size_t g0 = (rbase + row0) * D_MODEL + col;
        const size_t g1 = (rbase + row0 + 8) * D_MODEL + col;
        *reinterpret_cast<uint32_t*>(&Ch[g0]) = cvt_f16x2(v00, v01);
        *reinterpret_cast<uint32_t*>(&Ch[g1]) = cvt_f16x2(v10, v11);
        *reinterpret_cast<uint32_t*>(&Cl[g0]) =
            cvt_f16x2(v00 - h_rt(v00), v01 - h_rt(v01));
        *reinterpret_cast<uint32_t*>(&Cl[g1]) =
            cvt_f16x2(v10 - h_rt(v10), v11 - h_rt(v11));
    }
}

// ---------------------------------------------------------------------------
// Launch
// ---------------------------------------------------------------------------
extern "C" void kernel_launch(void* const* d_in, const int* in_sizes, int n_in,
                              void* d_out, int out_size)
{
    const float* x  = (const float*)d_in[0];
    const float* Wq = (const float*)d_in[1];
    const float* bq = (const float*)d_in[2];
    const float* Wk = (const float*)d_in[3];
    const float* bk = (const float*)d_in[4];
    const float* Wv = (const float*)d_in[5];
    const float* bv = (const float*)d_in[6];
    const float* Wo = (const float*)d_in[7];
    const float* bo = (const float*)d_in[8];
    float* out = (float*)d_out;

    __half *xh, *xl, *wh, *qh, *ql, *kh, *vh, *ch, *cl;
    cudaGetSymbolAddress((void**)&xh, g_xh);
    cudaGetSymbolAddress((void**)&xl, g_xl);
    cudaGetSymbolAddress((void**)&wh, g_wh);
    cudaGetSymbolAddress((void**)&qh, g_qh);
    cudaGetSymbolAddress((void**)&ql, g_ql);
    cudaGetSymbolAddress((void**)&kh, g_kh);
    cudaGetSymbolAddress((void**)&vh, g_vh);
    cudaGetSymbolAddress((void**)&ch, g_ch);
    cudaGetSymbolAddress((void**)&cl, g_cl);

    cudaFuncSetAttribute(gemm_qkv_kernel,
                         cudaFuncAttributeMaxDynamicSharedMemorySize,
                         SM_G2_TOTAL);
    cudaFuncSetAttribute(gemm_o_kernel,
                         cudaFuncAttributeMaxDynamicSharedMemorySize,
                         SM_GO_TOTAL);
    cudaFuncSetAttribute(attn_hmma_kernel,
                         cudaFuncAttributeMaxDynamicSharedMemorySize,
                         A_SM_TOTAL);

    dim3 split_grid((M_ROWS * D_MODEL / 16 + 255) / 256, 5);
    split_all_kernel<<<split_grid, 256>>>(x, Wq, Wk, Wv, Wo, xh, xl, wh);

    dim3 qkv_grid(M_ROWS / BM2, D_MODEL / BN2, 3);   // 32 x 6 x 3 = 576
    gemm_qkv_kernel<<<qkv_grid, 256, SM_G2_TOTAL>>>(
        xh, xl, wh, bq, bk, bv, qh, ql, kh, vh);

    dim3 attn_grid(S_LEN / 128, H_NUM, B_SZ);        // 16 x 12 x 2 = 384
    attn_hmma_kernel<<<attn_grid, 256, A_SM_TOTAL>>>(
        qh, ql, kh, vh, ch, cl);

    dim3 o_grid(M_ROWS / 64, D_MODEL / 128);         // 64 x 6 = 384
    gemm_o_kernel<<<o_grid, 256, SM_GO_TOTAL>>>(
        ch, cl, wh + 3 * W_ELEMS, bo, out);
}